// round 2
// baseline (speedup 1.0000x reference)
#include <cuda_runtime.h>

#define Dd  512
#define Sd  512
#define Bd  2
#define Hd  8
#define HDd 64

typedef unsigned long long u64;

// ---------------- scratch (device globals; no allocs allowed) ----------------
__device__ float g_Wq[Dd * Dd];      // Wq folded with Aq (per-head block)
__device__ float g_Wk[Dd * Dd];      // Wk folded with Ak
__device__ float g_bq[Dd];
__device__ float g_bk[Dd];
__device__ float g_qt[Bd * Sd * Dd]; // q_term
__device__ float g_kt[Bd * Sd * Dd]; // k_term
__device__ float g_v [Bd * Sd * Dd]; // v projection
__device__ float g_ctx[Bd * Sd * Dd];

// ---------------- packed f32x2 / f16x2 helpers ----------------
__device__ __forceinline__ void ffma2(u64& c, u64 a, u64 b) {
    asm("fma.rn.f32x2 %0, %1, %2, %0;" : "+l"(c) : "l"(a), "l"(b));
}
__device__ __forceinline__ u64 dup2(float a) {
    u64 d; asm("mov.b64 %0, {%1, %1};" : "=l"(d) : "f"(a)); return d;
}
__device__ __forceinline__ float2 unpk(u64 v) {
    float2 r; asm("mov.b64 {%0, %1}, %2;" : "=f"(r.x), "=f"(r.y) : "l"(v)); return r;
}

// acc += tanh(q_d + k_d)*av_d + tanh(q_{d+1} + k_{d+1})*av_{d+1}
// q2/k2 hold two consecutive fp32 values (lo = d, hi = d+1).
__device__ __forceinline__ void tanh_acc2(u64 q2, u64 k2, float ava, float avb, float& acc) {
    u64 x2;
    asm("add.rn.f32x2 %0, %1, %2;" : "=l"(x2) : "l"(q2), "l"(k2));
    float xa, xb;
    asm("mov.b64 {%0, %1}, %2;" : "=f"(xa), "=f"(xb) : "l"(x2));
    unsigned h2;  // cvt.rn.f16x2.f32 d, a, b -> hi = a, lo = b
    asm("cvt.rn.f16x2.f32 %0, %1, %2;" : "=r"(h2) : "f"(xb), "f"(xa));
    unsigned t2;
    asm("tanh.approx.f16x2 %0, %1;" : "=r"(t2) : "r"(h2));
    float ta, tb;
    asm("{ .reg .b16 l, h;\n\t"
        "  mov.b32 {l, h}, %2;\n\t"
        "  cvt.f32.f16 %0, l;\n\t"
        "  cvt.f32.f16 %1, h; }"
        : "=f"(ta), "=f"(tb) : "r"(t2));
    acc = fmaf(ta, ava, acc);
    acc = fmaf(tb, avb, acc);
}

// ---------------- fold kernel: Wd[r, h*64+c] = sum_j W[r, h*64+j] * A[j,c] ----
__global__ void fold_kernel(const float* __restrict__ W,
                            const float* __restrict__ A,
                            const float* __restrict__ bsrc,
                            int sel) {
    __shared__ float As[64 * 64];
    __shared__ float ws[64];
    int r = blockIdx.x, h = blockIdx.y, c = threadIdx.x;
    float* Wd = sel ? g_Wk : g_Wq;
    float* bd = sel ? g_bk : g_bq;

    for (int i = c; i < 64 * 64; i += 64) As[i] = A[i];
    ws[c] = W[r * Dd + h * 64 + c];
    __syncthreads();

    float acc = 0.f;
    #pragma unroll 16
    for (int j = 0; j < 64; j++) acc += ws[j] * As[j * 64 + c];
    Wd[r * Dd + h * 64 + c] = acc;

    if (r == 0) {
        float bacc = 0.f;
        #pragma unroll 16
        for (int j = 0; j < 64; j++) bacc += bsrc[h * 64 + j] * As[j * 64 + c];
        bd[h * 64 + c] = bacc;
    }
}

// ---------------- FFMA2 GEMM: C[1024,512] = A[1024,512] @ W[512,512] + bias
// 64m x 128n tile, 256 threads, 4m x 8n per thread, f32x2 packed FMA.
__device__ __forceinline__ void gemm_body(const float* __restrict__ A,
                                          const float* __restrict__ W,
                                          const float* __restrict__ bias,
                                          float* __restrict__ C) {
    __shared__ float As[16][68];    // As[k][m], padded
    __shared__ float Ws[16][132];   // Ws[k][n], padded
    int m0 = blockIdx.y * 64, n0 = blockIdx.x * 128;
    int tid = threadIdx.x;
    int tx = tid & 15, ty = tid >> 4;

    u64 acc[4][4];
    #pragma unroll
    for (int i = 0; i < 4; i++)
        #pragma unroll
        for (int j = 0; j < 4; j++) acc[i][j] = 0ull;

    for (int k0 = 0; k0 < Dd; k0 += 16) {
        {
            // A tile: 64m x 16k, transposed into As[k][m]
            int r  = tid & 63;
            int c4 = (tid >> 6) << 2;
            float4 a = *(const float4*)(A + (size_t)(m0 + r) * Dd + k0 + c4);
            As[c4 + 0][r] = a.x; As[c4 + 1][r] = a.y;
            As[c4 + 2][r] = a.z; As[c4 + 3][r] = a.w;
            // W tile: 16k x 128n
            int rw = tid >> 4, cw = (tid & 15) << 3;
            *(float4*)&Ws[rw][cw]     = *(const float4*)(W + (size_t)(k0 + rw) * Dd + n0 + cw);
            *(float4*)&Ws[rw][cw + 4] = *(const float4*)(W + (size_t)(k0 + rw) * Dd + n0 + cw + 4);
        }
        __syncthreads();
        #pragma unroll
        for (int k = 0; k < 16; k++) {
            float4 a4 = *(const float4*)&As[k][ty << 2];
            ulonglong2 b01 = *(const ulonglong2*)&Ws[k][tx << 3];
            ulonglong2 b23 = *(const ulonglong2*)&Ws[k][(tx << 3) + 4];
            u64 d0 = dup2(a4.x), d1 = dup2(a4.y), d2 = dup2(a4.z), d3 = dup2(a4.w);
            ffma2(acc[0][0], d0, b01.x); ffma2(acc[0][1], d0, b01.y);
            ffma2(acc[0][2], d0, b23.x); ffma2(acc[0][3], d0, b23.y);
            ffma2(acc[1][0], d1, b01.x); ffma2(acc[1][1], d1, b01.y);
            ffma2(acc[1][2], d1, b23.x); ffma2(acc[1][3], d1, b23.y);
            ffma2(acc[2][0], d2, b01.x); ffma2(acc[2][1], d2, b01.y);
            ffma2(acc[2][2], d2, b23.x); ffma2(acc[2][3], d2, b23.y);
            ffma2(acc[3][0], d3, b01.x); ffma2(acc[3][1], d3, b01.y);
            ffma2(acc[3][2], d3, b23.x); ffma2(acc[3][3], d3, b23.y);
        }
        __syncthreads();
    }

    float4 bb0 = *(const float4*)(bias + n0 + (tx << 3));
    float4 bb1 = *(const float4*)(bias + n0 + (tx << 3) + 4);
    #pragma unroll
    for (int i = 0; i < 4; i++) {
        float2 p0 = unpk(acc[i][0]), p1 = unpk(acc[i][1]);
        float2 p2 = unpk(acc[i][2]), p3 = unpk(acc[i][3]);
        float4 o0 = { p0.x + bb0.x, p0.y + bb0.y, p1.x + bb0.z, p1.y + bb0.w };
        float4 o1 = { p2.x + bb1.x, p2.y + bb1.y, p3.x + bb1.z, p3.y + bb1.w };
        float* crow = C + (size_t)(m0 + (ty << 2) + i) * Dd + n0 + (tx << 3);
        *(float4*)crow       = o0;
        *(float4*)(crow + 4) = o1;
    }
}

__global__ __launch_bounds__(256) void gemm_qkv_kernel(const float* __restrict__ qin,
                                                       const float* __restrict__ kin,
                                                       const float* __restrict__ vin,
                                                       const float* __restrict__ Wv,
                                                       const float* __restrict__ bv) {
    const float *A, *W, *bias;
    float* C;
    if (blockIdx.z == 0)      { A = qin; W = g_Wq; bias = g_bq; C = g_qt; }
    else if (blockIdx.z == 1) { A = kin; W = g_Wk; bias = g_bk; C = g_kt; }
    else                      { A = vin; W = Wv;   bias = bv;   C = g_v;  }
    gemm_body(A, W, bias, C);
}

__global__ __launch_bounds__(256) void gemm_out_kernel(const float* __restrict__ Wo,
                                                       const float* __restrict__ bo,
                                                       float* __restrict__ out) {
    gemm_body(g_ctx, Wo, bo, out);
}

// ---------------- fused scores + softmax + ctx ----------------
// 256 threads = 8 warps. TQ=16 q rows per block (2 per warp). CK=32 k per chunk
// (1 per lane). tanh in f16x2 (2 per MUFU op), fp32 accumulate.
#define TQ 16
#define CK 32

__global__ __launch_bounds__(256, 4) void attn_kernel(const float* __restrict__ av,
                                                      float* __restrict__ attn_out) {
    __shared__ float sc[TQ][Sd];        // 32 KB
    __shared__ float ks[CK][68];        // 8.5 KB
    __shared__ float qs[TQ][68];        // 4.25 KB
    __shared__ float avs[64];

    int b = blockIdx.z, h = blockIdx.y;
    int q0 = blockIdx.x * TQ;
    int tid = threadIdx.x;
    int w = tid >> 5, ln = tid & 31;
    int qr0 = 2 * w;

    // stage q terms (16 rows x 64 d = 1024 floats = 256 x float4)
    {
        int row = tid >> 4, d4 = (tid & 15) << 2;
        *(float4*)&qs[row][d4] =
            *(const float4*)(g_qt + ((size_t)(b * Sd + q0 + row)) * Dd + h * HDd + d4);
    }
    if (tid < 64) avs[tid] = av[tid];
    __syncthreads();

    // -------- scores --------
    for (int c0 = 0; c0 < Sd; c0 += CK) {
        // stage k-term chunk (32 rows x 64 d = 2048 floats = 256 x 2 float4)
        #pragma unroll
        for (int i = tid; i < CK * 16; i += 256) {
            int kk = i >> 4, d4 = (i & 15) << 2;
            *(float4*)&ks[kk][d4] =
                *(const float4*)(g_kt + ((size_t)(b * Sd + c0 + kk)) * Dd + h * HDd + d4);
        }
        __syncthreads();

        float acc0 = 0.f, acc1 = 0.f;
        #pragma unroll
        for (int d = 0; d < 64; d += 4) {
            ulonglong2 k2 = *(const ulonglong2*)&ks[ln][d];        // lane-distinct
            ulonglong2 qa = *(const ulonglong2*)&qs[qr0][d];       // warp broadcast
            ulonglong2 qb = *(const ulonglong2*)&qs[qr0 + 1][d];   // warp broadcast
            float4 avv = *(const float4*)&avs[d];                  // warp broadcast
            tanh_acc2(qa.x, k2.x, avv.x, avv.y, acc0);
            tanh_acc2(qa.y, k2.y, avv.z, avv.w, acc0);
            tanh_acc2(qb.x, k2.x, avv.x, avv.y, acc1);
            tanh_acc2(qb.y, k2.y, avv.z, avv.w, acc1);
        }
        sc[qr0][c0 + ln]     = acc0;
        sc[qr0 + 1][c0 + ln] = acc1;
        __syncthreads();
    }

    // -------- softmax per q row (warp per row, 2 rows/warp) --------
    for (int qq = w; qq < TQ; qq += 8) {
        float mx = -1e30f;
        for (int k = ln; k < Sd; k += 32) mx = fmaxf(mx, sc[qq][k]);
        #pragma unroll
        for (int o = 16; o > 0; o >>= 1) mx = fmaxf(mx, __shfl_xor_sync(0xffffffffu, mx, o));
        float sum = 0.f;
        for (int k = ln; k < Sd; k += 32) {
            float e = __expf(sc[qq][k] - mx);
            sc[qq][k] = e;
            sum += e;
        }
        #pragma unroll
        for (int o = 16; o > 0; o >>= 1) sum += __shfl_xor_sync(0xffffffffu, sum, o);
        float inv = 1.f / sum;
        float* arow = attn_out + (((size_t)(b * Hd + h) * Sd) + q0 + qq) * Sd;
        for (int k = ln; k < Sd; k += 32) {
            float a = sc[qq][k] * inv;
            sc[qq][k] = a;
            arow[k] = a;
        }
    }
    __syncthreads();

    // -------- ctx = attn @ v (head slice) --------
    int dd = tid & 63, qg = tid >> 6;  // qg in 0..3, each owns 4 q rows
    float c[4] = {0.f, 0.f, 0.f, 0.f};
    const float* vcol = g_v + (size_t)b * Sd * Dd + h * HDd + dd;
    for (int k = 0; k < Sd; k += 4) {
        float v0 = vcol[(size_t)(k + 0) * Dd];
        float v1 = vcol[(size_t)(k + 1) * Dd];
        float v2 = vcol[(size_t)(k + 2) * Dd];
        float v3 = vcol[(size_t)(k + 3) * Dd];
        #pragma unroll
        for (int i = 0; i < 4; i++) {
            float4 a = *(const float4*)&sc[qg * 4 + i][k];
            c[i] += a.x * v0 + a.y * v1 + a.z * v2 + a.w * v3;
        }
    }
    #pragma unroll
    for (int i = 0; i < 4; i++)
        g_ctx[((size_t)(b * Sd) + q0 + qg * 4 + i) * Dd + h * HDd + dd] = c[i];
}

// ---------------- launch ----------------
extern "C" void kernel_launch(void* const* d_in, const int* in_sizes, int n_in,
                              void* d_out, int out_size) {
    const float* query = (const float*)d_in[0];
    const float* key_  = (const float*)d_in[1];
    const float* value = (const float*)d_in[2];
    const float* Wq    = (const float*)d_in[3];
    const float* bq    = (const float*)d_in[4];
    const float* Wk    = (const float*)d_in[5];
    const float* bk    = (const float*)d_in[6];
    const float* Wv    = (const float*)d_in[7];
    const float* bv    = (const float*)d_in[8];
    const float* Wo    = (const float*)d_in[9];
    const float* bo    = (const float*)d_in[10];
    const float* Aq    = (const float*)d_in[11];
    const float* Ak    = (const float*)d_in[12];
    const float* av    = (const float*)d_in[13];

    float* out      = (float*)d_out;                  // [B,S,D]
    float* attn_out = out + (size_t)Bd * Sd * Dd;     // [B,H,S,S]

    fold_kernel<<<dim3(512, 8), 64>>>(Wq, Aq, bq, 0);
    fold_kernel<<<dim3(512, 8), 64>>>(Wk, Ak, bk, 1);
    gemm_qkv_kernel<<<dim3(4, 16, 3), 256>>>(query, key_, value, Wv, bv);
    attn_kernel<<<dim3(Sd / TQ, Hd, Bd), 256>>>(av, attn_out);
    gemm_out_kernel<<<dim3(4, 16), 256>>>(Wo, bo, out);
}

// round 3
// speedup vs baseline: 1.1925x; 1.1925x over previous
#include <cuda_runtime.h>
#include <cuda_fp16.h>

#define Dd  512
#define Sd  512
#define Bd  2
#define Hd  8
#define HDd 64

typedef unsigned long long u64;
typedef unsigned int u32;

// ---------------- scratch (device globals; no allocs allowed) ----------------
__device__ float  g_Wq[Dd * Dd];      // Wq folded with Aq
__device__ float  g_Wk[Dd * Dd];      // Wk folded with Ak
__device__ float  g_bq[Dd];
__device__ float  g_bk[Dd];
__device__ __half g_qth[Bd * Sd * Dd]; // q_term, f16
__device__ __half g_kth[Bd * Sd * Dd]; // k_term, f16
__device__ float  g_v  [Bd * Sd * Dd]; // v projection
__device__ float  g_ctx[Bd * Sd * Dd];

// ---------------- packed helpers ----------------
__device__ __forceinline__ void ffma2(u64& c, u64 a, u64 b) {
    asm("fma.rn.f32x2 %0, %1, %2, %0;" : "+l"(c) : "l"(a), "l"(b));
}
__device__ __forceinline__ u64 dup2(float a) {
    u64 d; asm("mov.b64 %0, {%1, %1};" : "=l"(d) : "f"(a)); return d;
}
__device__ __forceinline__ float2 unpk(u64 v) {
    float2 r; asm("mov.b64 {%0, %1}, %2;" : "=f"(r.x), "=f"(r.y) : "l"(v)); return r;
}

// acc += tanh(q_d + k_d)*av0 + tanh(q_{d+1} + k_{d+1})*av1   (q2/k2: f16x2 bits)
__device__ __forceinline__ void tacc(u32 q2, u32 k2, float av0, float av1, float& acc) {
    u32 x2, t2;
    asm("add.rn.f16x2 %0, %1, %2;" : "=r"(x2) : "r"(q2), "r"(k2));
    asm("tanh.approx.f16x2 %0, %1;" : "=r"(t2) : "r"(x2));
    float ta, tb;
    asm("{ .reg .b16 l, h;\n\t"
        "  mov.b32 {l, h}, %2;\n\t"
        "  cvt.f32.f16 %0, l;\n\t"
        "  cvt.f32.f16 %1, h; }"
        : "=f"(ta), "=f"(tb) : "r"(t2));
    acc = fmaf(ta, av0, acc);
    acc = fmaf(tb, av1, acc);
}

// ---------------- fold kernel: Wd[r, h*64+c] = sum_j W[r, h*64+j] * A[j,c] ----
__global__ void fold_kernel(const float* __restrict__ W,
                            const float* __restrict__ A,
                            const float* __restrict__ bsrc,
                            int sel) {
    __shared__ float As[64 * 64];
    __shared__ float ws[64];
    int r = blockIdx.x, h = blockIdx.y, c = threadIdx.x;
    float* Wd = sel ? g_Wk : g_Wq;
    float* bd = sel ? g_bk : g_bq;

    for (int i = c; i < 64 * 64; i += 64) As[i] = A[i];
    ws[c] = W[r * Dd + h * 64 + c];
    __syncthreads();

    float acc = 0.f;
    #pragma unroll 16
    for (int j = 0; j < 64; j++) acc += ws[j] * As[j * 64 + c];
    Wd[r * Dd + h * 64 + c] = acc;

    if (r == 0) {
        float bacc = 0.f;
        #pragma unroll 16
        for (int j = 0; j < 64; j++) bacc += bsrc[h * 64 + j] * As[j * 64 + c];
        bd[h * 64 + c] = bacc;
    }
}

// ---------------- FFMA2 GEMM, 64x64 tile, 256 threads, 4m x 4n per thread ----
template <bool HOUT>
__device__ __forceinline__ void gemm_body(const float* __restrict__ A,
                                          const float* __restrict__ W,
                                          const float* __restrict__ bias,
                                          float* __restrict__ C,
                                          __half* __restrict__ Ch) {
    __shared__ float As[16][68];   // As[k][m]
    __shared__ float Ws[16][68];   // Ws[k][n]
    int m0 = blockIdx.y * 64, n0 = blockIdx.x * 64;
    int tid = threadIdx.x;
    int tx = tid & 15, ty = tid >> 4;

    u64 acc[4][2];
    #pragma unroll
    for (int i = 0; i < 4; i++) { acc[i][0] = 0ull; acc[i][1] = 0ull; }

    for (int k0 = 0; k0 < Dd; k0 += 16) {
        {
            int r  = tid & 63;
            int c4 = (tid >> 6) << 2;
            float4 a = *(const float4*)(A + (size_t)(m0 + r) * Dd + k0 + c4);
            As[c4 + 0][r] = a.x; As[c4 + 1][r] = a.y;
            As[c4 + 2][r] = a.z; As[c4 + 3][r] = a.w;
            int rw = tid >> 4, cw = (tid & 15) << 2;
            *(float4*)&Ws[rw][cw] = *(const float4*)(W + (size_t)(k0 + rw) * Dd + n0 + cw);
        }
        __syncthreads();
        #pragma unroll
        for (int k = 0; k < 16; k++) {
            float4 a4 = *(const float4*)&As[k][ty << 2];
            ulonglong2 b2 = *(const ulonglong2*)&Ws[k][tx << 2];
            u64 d0 = dup2(a4.x), d1 = dup2(a4.y), d2 = dup2(a4.z), d3 = dup2(a4.w);
            ffma2(acc[0][0], d0, b2.x); ffma2(acc[0][1], d0, b2.y);
            ffma2(acc[1][0], d1, b2.x); ffma2(acc[1][1], d1, b2.y);
            ffma2(acc[2][0], d2, b2.x); ffma2(acc[2][1], d2, b2.y);
            ffma2(acc[3][0], d3, b2.x); ffma2(acc[3][1], d3, b2.y);
        }
        __syncthreads();
    }

    float4 bb = make_float4(0.f, 0.f, 0.f, 0.f);
    if (bias) bb = *(const float4*)(bias + n0 + (tx << 2));
    #pragma unroll
    for (int i = 0; i < 4; i++) {
        float2 p0 = unpk(acc[i][0]), p1 = unpk(acc[i][1]);
        float4 o = { p0.x + bb.x, p0.y + bb.y, p1.x + bb.z, p1.y + bb.w };
        size_t off = (size_t)(m0 + (ty << 2) + i) * Dd + n0 + (tx << 2);
        if (HOUT) {
            __half2 h0 = __floats2half2_rn(o.x, o.y);
            __half2 h1 = __floats2half2_rn(o.z, o.w);
            uint2 u;
            u.x = *(u32*)&h0; u.y = *(u32*)&h1;
            *(uint2*)(Ch + off) = u;
        } else {
            *(float4*)(C + off) = o;
        }
    }
}

// z = 0 -> q (f16 out), z = 1 -> k (f16 out)
__global__ __launch_bounds__(256) void gemm_qk_kernel(const float* __restrict__ qin,
                                                      const float* __restrict__ kin) {
    if (blockIdx.z == 0) gemm_body<true>(qin, g_Wq, g_bq, nullptr, g_qth);
    else                 gemm_body<true>(kin, g_Wk, g_bk, nullptr, g_kth);
}

__global__ __launch_bounds__(256) void gemm_v_kernel(const float* __restrict__ vin,
                                                     const float* __restrict__ Wv,
                                                     const float* __restrict__ bv) {
    gemm_body<false>(vin, Wv, bv, g_v, nullptr);
}

__global__ __launch_bounds__(256) void gemm_out_kernel(const float* __restrict__ Wo,
                                                       const float* __restrict__ bo,
                                                       float* __restrict__ out) {
    gemm_body<false>(g_ctx, Wo, bo, out, nullptr);
}

// ---------------- scores + softmax (registers), 512 thr = 16 warps = 16 q rows
__global__ __launch_bounds__(512) void scores_kernel(const float* __restrict__ av,
                                                     float* __restrict__ attn_out) {
    __shared__ __half ks[32][72];   // k chunk: 32 rows x 64 d (+8 pad)
    __shared__ __half qs[16][72];   // q rows
    __shared__ float  avs[64];

    int b = blockIdx.z, h = blockIdx.y;
    int q0 = blockIdx.x * 16;
    int tid = threadIdx.x;
    int w = tid >> 5, ln = tid & 31;

    // stage q rows: 16 rows x 64 halves; each thread loads 2 halves (u32)
    {
        int row = tid >> 5, c = (tid & 31) << 1;
        *(u32*)&qs[row][c] =
            *(const u32*)(g_qth + ((size_t)(b * Sd + q0 + row)) * Dd + h * HDd + c);
    }
    if (tid < 64) avs[tid] = av[tid];
    __syncthreads();

    float s[16];

    for (int c0 = 0; c0 < Sd; c0 += 32) {
        // stage k chunk: 32 rows x 64 halves; each thread 4 halves (uint2)
        {
            int row = tid >> 4, c = (tid & 15) << 2;
            *(uint2*)&ks[row][c] =
                *(const uint2*)(g_kth + ((size_t)(b * Sd + c0 + row)) * Dd + h * HDd + c);
        }
        __syncthreads();

        float acc = 0.f;
        #pragma unroll
        for (int j = 0; j < 8; j++) {
            uint4 kv = *(const uint4*)&ks[ln][j << 3];
            uint4 qv = *(const uint4*)&qs[w][j << 3];
            float4 a0 = *(const float4*)&avs[(j << 3)];
            float4 a1 = *(const float4*)&avs[(j << 3) + 4];
            tacc(qv.x, kv.x, a0.x, a0.y, acc);
            tacc(qv.y, kv.y, a0.z, a0.w, acc);
            tacc(qv.z, kv.z, a1.x, a1.y, acc);
            tacc(qv.w, kv.w, a1.z, a1.w, acc);
        }
        s[c0 >> 5] = acc;
        __syncthreads();
    }

    // softmax over the 512 scores of q row w (16 regs/lane)
    float mx = -1e30f;
    #pragma unroll
    for (int j = 0; j < 16; j++) mx = fmaxf(mx, s[j]);
    #pragma unroll
    for (int o = 16; o > 0; o >>= 1) mx = fmaxf(mx, __shfl_xor_sync(0xffffffffu, mx, o));
    float sum = 0.f;
    #pragma unroll
    for (int j = 0; j < 16; j++) { s[j] = __expf(s[j] - mx); sum += s[j]; }
    #pragma unroll
    for (int o = 16; o > 0; o >>= 1) sum += __shfl_xor_sync(0xffffffffu, sum, o);
    float inv = 1.f / sum;

    float* arow = attn_out + (((size_t)(b * Hd + h) * Sd) + q0 + w) * Sd;
    #pragma unroll
    for (int j = 0; j < 16; j++) arow[(j << 5) + ln] = s[j] * inv;
}

// ---------------- ctx = attn @ v (per (b,h)), FFMA2 64x64 tile ----------------
__global__ __launch_bounds__(256) void ctx_kernel(const float* __restrict__ attn) {
    __shared__ float As[16][68];   // As[k][q]
    __shared__ float Vs[16][68];   // Vs[k][d]
    int bh = blockIdx.y;
    int b = bh >> 3, h = bh & 7;
    int m0 = blockIdx.x * 64;
    const float* A = attn + (size_t)bh * Sd * Sd;
    const float* V = g_v + (size_t)b * Sd * Dd + h * HDd;
    float* Cc = g_ctx + (size_t)b * Sd * Dd + h * HDd;

    int tid = threadIdx.x;
    int tx = tid & 15, ty = tid >> 4;

    u64 acc[4][2];
    #pragma unroll
    for (int i = 0; i < 4; i++) { acc[i][0] = 0ull; acc[i][1] = 0ull; }

    for (int k0 = 0; k0 < Sd; k0 += 16) {
        {
            int r  = tid & 63;
            int c4 = (tid >> 6) << 2;
            float4 a = *(const float4*)(A + (size_t)(m0 + r) * Sd + k0 + c4);
            As[c4 + 0][r] = a.x; As[c4 + 1][r] = a.y;
            As[c4 + 2][r] = a.z; As[c4 + 3][r] = a.w;
            int rw = tid >> 4, cw = (tid & 15) << 2;
            *(float4*)&Vs[rw][cw] = *(const float4*)(V + (size_t)(k0 + rw) * Dd + cw);
        }
        __syncthreads();
        #pragma unroll
        for (int k = 0; k < 16; k++) {
            float4 a4 = *(const float4*)&As[k][ty << 2];
            ulonglong2 b2 = *(const ulonglong2*)&Vs[k][tx << 2];
            u64 d0 = dup2(a4.x), d1 = dup2(a4.y), d2 = dup2(a4.z), d3 = dup2(a4.w);
            ffma2(acc[0][0], d0, b2.x); ffma2(acc[0][1], d0, b2.y);
            ffma2(acc[1][0], d1, b2.x); ffma2(acc[1][1], d1, b2.y);
            ffma2(acc[2][0], d2, b2.x); ffma2(acc[2][1], d2, b2.y);
            ffma2(acc[3][0], d3, b2.x); ffma2(acc[3][1], d3, b2.y);
        }
        __syncthreads();
    }

    #pragma unroll
    for (int i = 0; i < 4; i++) {
        float2 p0 = unpk(acc[i][0]), p1 = unpk(acc[i][1]);
        float4 o = { p0.x, p0.y, p1.x, p1.y };
        *(float4*)(Cc + (size_t)(m0 + (ty << 2) + i) * Dd + (tx << 2)) = o;
    }
}

// ---------------- launch ----------------
extern "C" void kernel_launch(void* const* d_in, const int* in_sizes, int n_in,
                              void* d_out, int out_size) {
    const float* query = (const float*)d_in[0];
    const float* key_  = (const float*)d_in[1];
    const float* value = (const float*)d_in[2];
    const float* Wq    = (const float*)d_in[3];
    const float* bq    = (const float*)d_in[4];
    const float* Wk    = (const float*)d_in[5];
    const float* bk    = (const float*)d_in[6];
    const float* Wv    = (const float*)d_in[7];
    const float* bv    = (const float*)d_in[8];
    const float* Wo    = (const float*)d_in[9];
    const float* bo    = (const float*)d_in[10];
    const float* Aq    = (const float*)d_in[11];
    const float* Ak    = (const float*)d_in[12];
    const float* av    = (const float*)d_in[13];

    float* out      = (float*)d_out;                  // [B,S,D]
    float* attn_out = out + (size_t)Bd * Sd * Dd;     // [B,H,S,S]

    fold_kernel<<<dim3(512, 8), 64>>>(Wq, Aq, bq, 0);
    fold_kernel<<<dim3(512, 8), 64>>>(Wk, Ak, bk, 1);
    gemm_qk_kernel<<<dim3(8, 16, 2), 256>>>(query, key_);
    gemm_v_kernel<<<dim3(8, 16), 256>>>(value, Wv, bv);
    scores_kernel<<<dim3(32, Hd, Bd), 512>>>(av, attn_out);
    ctx_kernel<<<dim3(8, 16), 256>>>(attn_out);
    gemm_out_kernel<<<dim3(8, 16), 256>>>(Wo, bo, out);
}

// round 4
// speedup vs baseline: 1.4769x; 1.2385x over previous
#include <cuda_runtime.h>
#include <cuda_fp16.h>

#define Dd  512
#define Sd  512
#define Bd  2
#define Hd  8
#define HDd 64

typedef unsigned long long u64;
typedef unsigned int u32;

// ---------------- scratch (device globals) ----------------
__device__ __half g_Wqh[Dd * Dd];     // folded Wq@Aq, TRANSPOSED [n][k], f16
__device__ __half g_Wkh[Dd * Dd];     // folded Wk@Ak, transposed, f16
__device__ float  g_bq[Dd];
__device__ float  g_bk[Dd];
__device__ __half g_xq16[Bd * Sd * Dd]; // query input, f16
__device__ __half g_xk16[Bd * Sd * Dd]; // key input, f16
__device__ __half g_qth[Bd * Sd * Dd];  // q_term, f16
__device__ __half g_kth[Bd * Sd * Dd];  // k_term, f16
__device__ float  g_v  [Bd * Sd * Dd];
__device__ float  g_ctx[Bd * Sd * Dd];

// ---------------- helpers ----------------
__device__ __forceinline__ void ffma2(u64& c, u64 a, u64 b) {
    asm("fma.rn.f32x2 %0, %1, %2, %0;" : "+l"(c) : "l"(a), "l"(b));
}
__device__ __forceinline__ u64 dup2(float a) {
    u64 d; asm("mov.b64 %0, {%1, %1};" : "=l"(d) : "f"(a)); return d;
}
__device__ __forceinline__ float2 unpk(u64 v) {
    float2 r; asm("mov.b64 {%0, %1}, %2;" : "=f"(r.x), "=f"(r.y) : "l"(v)); return r;
}
__device__ __forceinline__ void h2f2(u32 h, float& lo, float& hi) {
    asm("{ .reg .b16 l, h;\n\t mov.b32 {l, h}, %2;\n\t"
        " cvt.f32.f16 %0, l;\n\t cvt.f32.f16 %1, h; }"
        : "=f"(lo), "=f"(hi) : "r"(h));
}
// acch(f16x2) += tanh(q2 + k2) * a2   (all f16x2)
__device__ __forceinline__ void tchain(u32 q2, u32 k2, u32 a2, u32& acch) {
    u32 x2, t2;
    asm("add.rn.f16x2 %0, %1, %2;" : "=r"(x2) : "r"(q2), "r"(k2));
    asm("tanh.approx.f16x2 %0, %1;" : "=r"(t2) : "r"(x2));
    asm("fma.rn.f16x2 %0, %1, %2, %0;" : "+r"(acch) : "r"(t2), "r"(a2));
}
__device__ __forceinline__ void mma16816(float* d, const u32* a, const u32* b) {
    asm volatile(
        "mma.sync.aligned.m16n8k16.row.col.f32.f16.f16.f32 "
        "{%0,%1,%2,%3}, {%4,%5,%6,%7}, {%8,%9}, {%0,%1,%2,%3};"
        : "+f"(d[0]), "+f"(d[1]), "+f"(d[2]), "+f"(d[3])
        : "r"(a[0]), "r"(a[1]), "r"(a[2]), "r"(a[3]), "r"(b[0]), "r"(b[1]));
}

// ---------------- cvt: query/key fp32 -> f16 ----------------
__global__ __launch_bounds__(256) void cvt_kernel(const float* __restrict__ q,
                                                  const float* __restrict__ k) {
    int t = blockIdx.x * 256 + threadIdx.x;           // 0..131071
    const float* src = (t < 65536) ? q : k;
    __half* dst = (t < 65536) ? g_xq16 : g_xk16;
    int base = (t & 65535) * 8;
    float4 a = *(const float4*)(src + base);
    float4 b = *(const float4*)(src + base + 4);
    __half2 h0 = __floats2half2_rn(a.x, a.y), h1 = __floats2half2_rn(a.z, a.w);
    __half2 h2 = __floats2half2_rn(b.x, b.y), h3 = __floats2half2_rn(b.z, b.w);
    uint4 u;
    u.x = *(u32*)&h0; u.y = *(u32*)&h1; u.z = *(u32*)&h2; u.w = *(u32*)&h3;
    *(uint4*)(dst + base) = u;
}

// ---------------- fold: Wfold[n][k] = sum_j W[k, h*64+j]*A[j, n-h*64], f16, transposed
__global__ void fold_kernel(const float* __restrict__ Wq, const float* __restrict__ Aq,
                            const float* __restrict__ bqi,
                            const float* __restrict__ Wk, const float* __restrict__ Ak,
                            const float* __restrict__ bki) {
    __shared__ float As[64 * 64];
    __shared__ float ws[64];
    int sel = blockIdx.z;
    const float* W = sel ? Wk : Wq;
    const float* A = sel ? Ak : Aq;
    const float* bs = sel ? bki : bqi;
    __half* Wd = sel ? g_Wkh : g_Wqh;
    float* bd = sel ? g_bk : g_bq;

    int r = blockIdx.x, h = blockIdx.y, c = threadIdx.x;
    for (int i = c; i < 64 * 64; i += 64) As[i] = A[i];
    ws[c] = W[r * Dd + h * 64 + c];
    __syncthreads();

    float acc = 0.f;
    #pragma unroll 16
    for (int j = 0; j < 64; j++) acc += ws[j] * As[j * 64 + c];
    Wd[(size_t)(h * 64 + c) * Dd + r] = __float2half(acc);   // transposed [n][k]

    if (r == 0) {
        float bacc = 0.f;
        #pragma unroll 16
        for (int j = 0; j < 64; j++) bacc += bs[h * 64 + j] * As[j * 64 + c];
        bd[h * 64 + c] = bacc;
    }
}

// ---------------- qk projection via HMMA: out = x16 @ Wfold^T + bias, f16 out
// 64m x 64n tile, 256 thr (8 warps: 2x4), k-chunks of 32, double-buffered.
__global__ __launch_bounds__(256) void qk_mma_kernel() {
    __shared__ __half As[2][64][40];
    __shared__ __half Bs[2][64][40];
    int z = blockIdx.z;
    const __half* X  = z ? g_xk16 : g_xq16;
    const __half* Wh = z ? g_Wkh : g_Wqh;
    const float* bias = z ? g_bk : g_bq;
    __half* out = z ? g_kth : g_qth;

    int m0 = blockIdx.y * 64, n0 = blockIdx.x * 64;
    int tid = threadIdx.x, wid = tid >> 5, lane = tid & 31;
    int wm = (wid & 1) * 32, wn = (wid >> 1) * 16;
    int g = lane >> 2, qd = (lane & 3) * 2;

    int sr = tid >> 2, sk = (tid & 3) * 8;   // stager: row, k-col (halves)

    float acc[2][2][4] = {};

    // chunk 0
    {
        uint4 ua = *(const uint4*)(X  + (size_t)(m0 + sr) * Dd + sk);
        uint4 uw = *(const uint4*)(Wh + (size_t)(n0 + sr) * Dd + sk);
        *(uint4*)&As[0][sr][sk] = ua;
        *(uint4*)&Bs[0][sr][sk] = uw;
    }
    __syncthreads();

    for (int ch = 0; ch < 16; ch++) {
        int buf = ch & 1;
        bool pf = ch < 15;
        uint4 ua, uw;
        if (pf) {
            int k0 = (ch + 1) * 32;
            ua = *(const uint4*)(X  + (size_t)(m0 + sr) * Dd + k0 + sk);
            uw = *(const uint4*)(Wh + (size_t)(n0 + sr) * Dd + k0 + sk);
        }
        #pragma unroll
        for (int ks = 0; ks < 32; ks += 16) {
            u32 a[2][4], b[2][2];
            #pragma unroll
            for (int mm = 0; mm < 2; mm++) {
                a[mm][0] = *(const u32*)&As[buf][wm + mm * 16 + g][ks + qd];
                a[mm][1] = *(const u32*)&As[buf][wm + mm * 16 + g + 8][ks + qd];
                a[mm][2] = *(const u32*)&As[buf][wm + mm * 16 + g][ks + qd + 8];
                a[mm][3] = *(const u32*)&As[buf][wm + mm * 16 + g + 8][ks + qd + 8];
            }
            #pragma unroll
            for (int nn = 0; nn < 2; nn++) {
                b[nn][0] = *(const u32*)&Bs[buf][wn + nn * 8 + g][ks + qd];
                b[nn][1] = *(const u32*)&Bs[buf][wn + nn * 8 + g][ks + qd + 8];
            }
            mma16816(acc[0][0], a[0], b[0]); mma16816(acc[0][1], a[0], b[1]);
            mma16816(acc[1][0], a[1], b[0]); mma16816(acc[1][1], a[1], b[1]);
        }
        if (pf) {
            __syncthreads();
            *(uint4*)&As[buf ^ 1][sr][sk] = ua;
            *(uint4*)&Bs[buf ^ 1][sr][sk] = uw;
            __syncthreads();
        }
    }

    // epilogue: +bias, cvt f16, store
    #pragma unroll
    for (int mm = 0; mm < 2; mm++) {
        #pragma unroll
        for (int nn = 0; nn < 2; nn++) {
            int M = m0 + wm + mm * 16;
            int N = n0 + wn + nn * 8 + qd;
            float b0 = bias[N], b1 = bias[N + 1];
            __half2 h01 = __floats2half2_rn(acc[mm][nn][0] + b0, acc[mm][nn][1] + b1);
            __half2 h23 = __floats2half2_rn(acc[mm][nn][2] + b0, acc[mm][nn][3] + b1);
            *(u32*)(out + (size_t)(M + g) * Dd + N)     = *(u32*)&h01;
            *(u32*)(out + (size_t)(M + g + 8) * Dd + N) = *(u32*)&h23;
        }
    }
}

// ---------------- FFMA2 GEMM body: 32m x 64n tile, 128 threads, K=512 ----------------
__device__ __forceinline__ void gemm32_body(const float* __restrict__ A, int lda,
                                            const float* __restrict__ W, int ldw,
                                            const float* __restrict__ bias,
                                            float* __restrict__ C, int ldc,
                                            int m0, int n0) {
    __shared__ float As[2][32][36];   // As[k][m]
    __shared__ float Ws[2][32][68];   // Ws[k][n]
    int tid = threadIdx.x;
    int tx = tid & 15, ty = tid >> 4;           // tx: n quad, ty: m quad (0..7)
    int ar = tid & 31, ac = (tid >> 5) << 2;    // A stage: row ar, k cols {ac, ac+16}
    int wr = tid >> 4, wc = (tid & 15) << 2;    // W stage: rows wr+{0,8,16,24}, col wc

    u64 acc[4][2];
    #pragma unroll
    for (int i = 0; i < 4; i++) { acc[i][0] = 0ull; acc[i][1] = 0ull; }

    float4 pa0, pa1, pw0, pw1, pw2, pw3;
    pa0 = *(const float4*)(A + (size_t)(m0 + ar) * lda + ac);
    pa1 = *(const float4*)(A + (size_t)(m0 + ar) * lda + ac + 16);
    pw0 = *(const float4*)(W + (size_t)(wr)      * ldw + n0 + wc);
    pw1 = *(const float4*)(W + (size_t)(wr + 8)  * ldw + n0 + wc);
    pw2 = *(const float4*)(W + (size_t)(wr + 16) * ldw + n0 + wc);
    pw3 = *(const float4*)(W + (size_t)(wr + 24) * ldw + n0 + wc);
    {
        As[0][ac + 0][ar] = pa0.x; As[0][ac + 1][ar] = pa0.y;
        As[0][ac + 2][ar] = pa0.z; As[0][ac + 3][ar] = pa0.w;
        As[0][ac + 16][ar] = pa1.x; As[0][ac + 17][ar] = pa1.y;
        As[0][ac + 18][ar] = pa1.z; As[0][ac + 19][ar] = pa1.w;
        *(float4*)&Ws[0][wr][wc]      = pw0;
        *(float4*)&Ws[0][wr + 8][wc]  = pw1;
        *(float4*)&Ws[0][wr + 16][wc] = pw2;
        *(float4*)&Ws[0][wr + 24][wc] = pw3;
    }
    __syncthreads();

    for (int ch = 0; ch < 16; ch++) {
        int buf = ch & 1;
        bool pf = ch < 15;
        if (pf) {
            int k0 = (ch + 1) * 32;
            pa0 = *(const float4*)(A + (size_t)(m0 + ar) * lda + k0 + ac);
            pa1 = *(const float4*)(A + (size_t)(m0 + ar) * lda + k0 + ac + 16);
            pw0 = *(const float4*)(W + (size_t)(k0 + wr)      * ldw + n0 + wc);
            pw1 = *(const float4*)(W + (size_t)(k0 + wr + 8)  * ldw + n0 + wc);
            pw2 = *(const float4*)(W + (size_t)(k0 + wr + 16) * ldw + n0 + wc);
            pw3 = *(const float4*)(W + (size_t)(k0 + wr + 24) * ldw + n0 + wc);
        }
        #pragma unroll
        for (int k = 0; k < 32; k++) {
            float4 a4 = *(const float4*)&As[buf][k][ty << 2];
            u64 blo = *(const u64*)&Ws[buf][k][tx << 1];
            u64 bhi = *(const u64*)&Ws[buf][k][(tx << 1) + 32];
            u64 d0 = dup2(a4.x), d1 = dup2(a4.y), d2 = dup2(a4.z), d3 = dup2(a4.w);
            ffma2(acc[0][0], d0, blo); ffma2(acc[0][1], d0, bhi);
            ffma2(acc[1][0], d1, blo); ffma2(acc[1][1], d1, bhi);
            ffma2(acc[2][0], d2, blo); ffma2(acc[2][1], d2, bhi);
            ffma2(acc[3][0], d3, blo); ffma2(acc[3][1], d3, bhi);
        }
        if (pf) {
            __syncthreads();
            int nb = buf ^ 1;
            As[nb][ac + 0][ar] = pa0.x; As[nb][ac + 1][ar] = pa0.y;
            As[nb][ac + 2][ar] = pa0.z; As[nb][ac + 3][ar] = pa0.w;
            As[nb][ac + 16][ar] = pa1.x; As[nb][ac + 17][ar] = pa1.y;
            As[nb][ac + 18][ar] = pa1.z; As[nb][ac + 19][ar] = pa1.w;
            *(float4*)&Ws[nb][wr][wc]      = pw0;
            *(float4*)&Ws[nb][wr + 8][wc]  = pw1;
            *(float4*)&Ws[nb][wr + 16][wc] = pw2;
            *(float4*)&Ws[nb][wr + 24][wc] = pw3;
            __syncthreads();
        }
    }

    int nlo = n0 + (tx << 1), nhi = nlo + 32;
    float bl0 = 0.f, bl1 = 0.f, bh0 = 0.f, bh1 = 0.f;
    if (bias) { bl0 = bias[nlo]; bl1 = bias[nlo + 1]; bh0 = bias[nhi]; bh1 = bias[nhi + 1]; }
    #pragma unroll
    for (int i = 0; i < 4; i++) {
        float2 plo = unpk(acc[i][0]);
        float2 phi = unpk(acc[i][1]);
        int row = m0 + (ty << 2) + i;
        float2 olo = { plo.x + bl0, plo.y + bl1 };
        float2 ohi = { phi.x + bh0, phi.y + bh1 };
        *(float2*)(C + (size_t)row * ldc + nlo) = olo;
        *(float2*)(C + (size_t)row * ldc + nhi) = ohi;
    }
}

__global__ __launch_bounds__(128) void gemm_v_kernel(const float* __restrict__ vin,
                                                     const float* __restrict__ Wv,
                                                     const float* __restrict__ bv) {
    gemm32_body(vin, Dd, Wv, Dd, bv, g_v, Dd, blockIdx.y * 32, blockIdx.x * 64);
}

__global__ __launch_bounds__(128) void ctx_kernel(const float* __restrict__ attn) {
    int bh = blockIdx.y;
    int b = bh >> 3, h = bh & 7;
    const float* A = attn + (size_t)bh * Sd * Sd;
    const float* V = g_v + (size_t)b * Sd * Dd + h * HDd;
    float* Cc = g_ctx + (size_t)b * Sd * Dd + h * HDd;
    gemm32_body(A, Sd, V, Dd, nullptr, Cc, Dd, blockIdx.x * 32, 0);
}

__global__ __launch_bounds__(128) void gemm_out_kernel(const float* __restrict__ Wo,
                                                       const float* __restrict__ bo,
                                                       float* __restrict__ out) {
    gemm32_body(g_ctx, Dd, Wo, Dd, bo, out, Dd, blockIdx.y * 32, blockIdx.x * 64);
}

// ---------------- scores + softmax, 512 thr = 16 warps = 16 q rows ----------------
__global__ __launch_bounds__(512, 2) void scores_kernel(const float* __restrict__ av,
                                                        float* __restrict__ attn_out) {
    __shared__ __half  ks[32][72];
    __shared__ __half  qs[16][72];
    __shared__ __half2 avh[32];

    int b = blockIdx.z, h = blockIdx.y;
    int q0 = blockIdx.x * 16;
    int tid = threadIdx.x;
    int w = tid >> 5, ln = tid & 31;

    if (tid < 32) avh[tid] = __floats2half2_rn(av[2 * tid], av[2 * tid + 1]);
    {
        int row = tid >> 5, c = (tid & 31) << 1;
        *(u32*)&qs[row][c] =
            *(const u32*)(g_qth + ((size_t)(b * Sd + q0 + row)) * Dd + h * HDd + c);
    }
    __syncthreads();

    float s[16];

    for (int c0 = 0; c0 < Sd; c0 += 32) {
        {
            int row = tid >> 4, c = (tid & 15) << 2;
            *(uint2*)&ks[row][c] =
                *(const uint2*)(g_kth + ((size_t)(b * Sd + c0 + row)) * Dd + h * HDd + c);
        }
        __syncthreads();

        float acc = 0.f;
        #pragma unroll
        for (int jc = 0; jc < 8; jc++) {
            uint4 kk = *(const uint4*)&ks[ln][jc << 3];
            uint4 qq = *(const uint4*)&qs[w][jc << 3];
            uint4 aa = *(const uint4*)&avh[jc << 2];
            u32 acch = 0;
            tchain(qq.x, kk.x, aa.x, acch);
            tchain(qq.y, kk.y, aa.y, acch);
            tchain(qq.z, kk.z, aa.z, acch);
            tchain(qq.w, kk.w, aa.w, acch);
            float lo, hi; h2f2(acch, lo, hi);
            acc += lo; acc += hi;
        }
        s[c0 >> 5] = acc;
        __syncthreads();
    }

    // softmax over the 512 scores of q row w
    float mx = -1e30f;
    #pragma unroll
    for (int j = 0; j < 16; j++) mx = fmaxf(mx, s[j]);
    #pragma unroll
    for (int o = 16; o > 0; o >>= 1) mx = fmaxf(mx, __shfl_xor_sync(0xffffffffu, mx, o));
    float sum = 0.f;
    #pragma unroll
    for (int j = 0; j < 16; j++) { s[j] = __expf(s[j] - mx); sum += s[j]; }
    #pragma unroll
    for (int o = 16; o > 0; o >>= 1) sum += __shfl_xor_sync(0xffffffffu, sum, o);
    float inv = 1.f / sum;

    float* arow = attn_out + (((size_t)(b * Hd + h) * Sd) + q0 + w) * Sd;
    #pragma unroll
    for (int j = 0; j < 16; j++) arow[(j << 5) + ln] = s[j] * inv;
}

// ---------------- launch ----------------
extern "C" void kernel_launch(void* const* d_in, const int* in_sizes, int n_in,
                              void* d_out, int out_size) {
    const float* query = (const float*)d_in[0];
    const float* key_  = (const float*)d_in[1];
    const float* value = (const float*)d_in[2];
    const float* Wq    = (const float*)d_in[3];
    const float* bq    = (const float*)d_in[4];
    const float* Wk    = (const float*)d_in[5];
    const float* bk    = (const float*)d_in[6];
    const float* Wv    = (const float*)d_in[7];
    const float* bv    = (const float*)d_in[8];
    const float* Wo    = (const float*)d_in[9];
    const float* bo    = (const float*)d_in[10];
    const float* Aq    = (const float*)d_in[11];
    const float* Ak    = (const float*)d_in[12];
    const float* av    = (const float*)d_in[13];

    float* out      = (float*)d_out;                  // [B,S,D]
    float* attn_out = out + (size_t)Bd * Sd * Dd;     // [B,H,S,S]

    cvt_kernel<<<512, 256>>>(query, key_);
    fold_kernel<<<dim3(512, 8, 2), 64>>>(Wq, Aq, bq, Wk, Ak, bk);
    qk_mma_kernel<<<dim3(8, 16, 2), 256>>>();
    gemm_v_kernel<<<dim3(8, 32), 128>>>(value, Wv, bv);
    scores_kernel<<<dim3(32, Hd, Bd), 512>>>(av, attn_out);
    ctx_kernel<<<dim3(16, 16), 128>>>(attn_out);
    gemm_out_kernel<<<dim3(8, 32), 128>>>(Wo, bo, out);
}

// round 5
// speedup vs baseline: 1.9819x; 1.3419x over previous
#include <cuda_runtime.h>
#include <cuda_fp16.h>

#define Dd  512
#define Sd  512
#define Bd  2
#define Hd  8
#define HDd 64

typedef unsigned long long u64;
typedef unsigned int u32;

// ---------------- scratch (device globals) ----------------
__device__ __half g_Wqh[Dd * Dd];       // folded Wq@Aq, transposed [n][k], f16
__device__ __half g_Wkh[Dd * Dd];       // folded Wk@Ak, transposed [n][k], f16
__device__ __half g_Wvh[Dd * Dd];       // Wv transposed [n][k], f16
__device__ __half g_Woh[Dd * Dd];       // Wo transposed [n][k], f16
__device__ float  g_bq[Dd];
__device__ float  g_bk[Dd];
__device__ __half g_xq16[Bd * Sd * Dd];
__device__ __half g_xk16[Bd * Sd * Dd];
__device__ __half g_xv16[Bd * Sd * Dd];
__device__ __half g_qth[Bd * Sd * Dd];  // q_term f16, row-major [b*S+q][D]
__device__ __half g_kth[Bd * Sd * Dd];  // k_term f16
__device__ __half g_v16T[Bd * Hd * HDd * Sd]; // v, per (b,h) transposed [d][s]
__device__ __half g_att16[Bd * Hd * Sd * Sd]; // attn weights f16 (16 MB)
__device__ __half g_ctx16[Bd * Sd * Dd];      // ctx f16, row-major

// ---------------- helpers ----------------
__device__ __forceinline__ void h2f2(u32 h, float& lo, float& hi) {
    asm("{ .reg .b16 l, h;\n\t mov.b32 {l, h}, %2;\n\t"
        " cvt.f32.f16 %0, l;\n\t cvt.f32.f16 %1, h; }"
        : "=f"(lo), "=f"(hi) : "r"(h));
}
// acch(f16x2) += tanh(q2 + k2) * a2   (all f16x2)
__device__ __forceinline__ void tchain(u32 q2, u32 k2, u32 a2, u32& acch) {
    u32 x2, t2;
    asm("add.rn.f16x2 %0, %1, %2;" : "=r"(x2) : "r"(q2), "r"(k2));
    asm("tanh.approx.f16x2 %0, %1;" : "=r"(t2) : "r"(x2));
    asm("fma.rn.f16x2 %0, %1, %2, %0;" : "+r"(acch) : "r"(t2), "r"(a2));
}
__device__ __forceinline__ void mma16816(float* d, const u32* a, const u32* b) {
    asm volatile(
        "mma.sync.aligned.m16n8k16.row.col.f32.f16.f16.f32 "
        "{%0,%1,%2,%3}, {%4,%5,%6,%7}, {%8,%9}, {%0,%1,%2,%3};"
        : "+f"(d[0]), "+f"(d[1]), "+f"(d[2]), "+f"(d[3])
        : "r"(a[0]), "r"(a[1]), "r"(a[2]), "r"(a[3]), "r"(b[0]), "r"(b[1]));
}

// ---------------- cvt: query/key/value fp32 -> f16 ----------------
__global__ __launch_bounds__(256) void cvt_kernel(const float* __restrict__ q,
                                                  const float* __restrict__ k,
                                                  const float* __restrict__ v) {
    int t = blockIdx.x * 256 + threadIdx.x;          // 0..196607
    int sel = t >> 16;
    const float* src = (sel == 0) ? q : (sel == 1) ? k : v;
    __half* dst = (sel == 0) ? g_xq16 : (sel == 1) ? g_xk16 : g_xv16;
    int base = (t & 65535) * 8;
    float4 a = *(const float4*)(src + base);
    float4 b = *(const float4*)(src + base + 4);
    __half2 h0 = __floats2half2_rn(a.x, a.y), h1 = __floats2half2_rn(a.z, a.w);
    __half2 h2 = __floats2half2_rn(b.x, b.y), h3 = __floats2half2_rn(b.z, b.w);
    uint4 u;
    u.x = *(u32*)&h0; u.y = *(u32*)&h1; u.z = *(u32*)&h2; u.w = *(u32*)&h3;
    *(uint4*)(dst + base) = u;
}

// ---------------- fold: Wd[n][k] = sum_j W[k, h*64+j]*A[j, n&63], f16 transposed
__global__ void fold_kernel(const float* __restrict__ Wq, const float* __restrict__ Aq,
                            const float* __restrict__ bqi,
                            const float* __restrict__ Wk, const float* __restrict__ Ak,
                            const float* __restrict__ bki) {
    __shared__ float As[64 * 64];
    __shared__ float ws[64];
    int sel = blockIdx.z;
    const float* W = sel ? Wk : Wq;
    const float* A = sel ? Ak : Aq;
    const float* bs = sel ? bki : bqi;
    __half* Wd = sel ? g_Wkh : g_Wqh;
    float* bd = sel ? g_bk : g_bq;

    int r = blockIdx.x, h = blockIdx.y, c = threadIdx.x;
    for (int i = c; i < 64 * 64; i += 64) As[i] = A[i];
    ws[c] = W[r * Dd + h * 64 + c];
    __syncthreads();

    float acc = 0.f;
    #pragma unroll 16
    for (int j = 0; j < 64; j++) acc += ws[j] * As[j * 64 + c];
    Wd[(size_t)(h * 64 + c) * Dd + r] = __float2half(acc);

    if (r == 0) {
        float bacc = 0.f;
        #pragma unroll 16
        for (int j = 0; j < 64; j++) bacc += bs[h * 64 + j] * As[j * 64 + c];
        bd[h * 64 + c] = bacc;
    }
}

// ---------------- wcvt: Wv/Wo [k][n] fp32 -> [n][k] f16 (smem transpose) ----
__global__ __launch_bounds__(256) void wcvt_kernel(const float* __restrict__ Wv,
                                                   const float* __restrict__ Wo) {
    __shared__ float Ts[32][33];
    int z = blockIdx.z;
    const float* src = z ? Wo : Wv;
    __half* dst = z ? g_Woh : g_Wvh;
    int k0 = blockIdx.y * 32, n0 = blockIdx.x * 32;
    int tid = threadIdx.x;
    int r = tid >> 3, c4 = (tid & 7) << 2;

    float4 w = *(const float4*)(src + (size_t)(k0 + r) * Dd + n0 + c4);
    Ts[r][c4 + 0] = w.x; Ts[r][c4 + 1] = w.y;
    Ts[r][c4 + 2] = w.z; Ts[r][c4 + 3] = w.w;
    __syncthreads();

    __half2 h0 = __floats2half2_rn(Ts[c4 + 0][r], Ts[c4 + 1][r]);
    __half2 h1 = __floats2half2_rn(Ts[c4 + 2][r], Ts[c4 + 3][r]);
    uint2 u; u.x = *(u32*)&h0; u.y = *(u32*)&h1;
    *(uint2*)(dst + (size_t)(n0 + r) * Dd + k0 + c4) = u;
}

// ---------------- HMMA tile body: 64m x 64n, K=512, double-buffered ----------
// X row-major [m][k] (lda), BT row-major [n][k] (ldb).
// MODE 0: f16 out row-major (outh, ldo) + bias
// MODE 1: f16 out transposed per (b,h): v16T[(bb*8+h)*64+dd][s] + bias
// MODE 2: f32 out row-major (outf, ldo) + bias
template <int MODE>
__device__ __forceinline__ void mma_tile(const __half* __restrict__ X, int lda,
                                         const __half* __restrict__ BT, int ldb,
                                         const float* __restrict__ bias,
                                         __half* __restrict__ outh,
                                         float* __restrict__ outf,
                                         int m0, int n0, int ldo) {
    __shared__ __half As[2][64][40];
    __shared__ __half Bs[2][64][40];
    int tid = threadIdx.x, wid = tid >> 5, lane = tid & 31;
    int wm = (wid & 1) * 32, wn = (wid >> 1) * 16;
    int g = lane >> 2, qd = (lane & 3) * 2;
    int sr = tid >> 2, sk = (tid & 3) * 8;

    float acc[2][2][4] = {};

    {
        uint4 ua = *(const uint4*)(X  + (size_t)(m0 + sr) * lda + sk);
        uint4 uw = *(const uint4*)(BT + (size_t)(n0 + sr) * ldb + sk);
        *(uint4*)&As[0][sr][sk] = ua;
        *(uint4*)&Bs[0][sr][sk] = uw;
    }
    __syncthreads();

    for (int ch = 0; ch < 16; ch++) {
        int buf = ch & 1;
        bool pf = ch < 15;
        uint4 ua, uw;
        if (pf) {
            int k0 = (ch + 1) * 32;
            ua = *(const uint4*)(X  + (size_t)(m0 + sr) * lda + k0 + sk);
            uw = *(const uint4*)(BT + (size_t)(n0 + sr) * ldb + k0 + sk);
        }
        #pragma unroll
        for (int ks = 0; ks < 32; ks += 16) {
            u32 a[2][4], b[2][2];
            #pragma unroll
            for (int mm = 0; mm < 2; mm++) {
                a[mm][0] = *(const u32*)&As[buf][wm + mm * 16 + g][ks + qd];
                a[mm][1] = *(const u32*)&As[buf][wm + mm * 16 + g + 8][ks + qd];
                a[mm][2] = *(const u32*)&As[buf][wm + mm * 16 + g][ks + qd + 8];
                a[mm][3] = *(const u32*)&As[buf][wm + mm * 16 + g + 8][ks + qd + 8];
            }
            #pragma unroll
            for (int nn = 0; nn < 2; nn++) {
                b[nn][0] = *(const u32*)&Bs[buf][wn + nn * 8 + g][ks + qd];
                b[nn][1] = *(const u32*)&Bs[buf][wn + nn * 8 + g][ks + qd + 8];
            }
            mma16816(acc[0][0], a[0], b[0]); mma16816(acc[0][1], a[0], b[1]);
            mma16816(acc[1][0], a[1], b[0]); mma16816(acc[1][1], a[1], b[1]);
        }
        if (pf) {
            __syncthreads();
            *(uint4*)&As[buf ^ 1][sr][sk] = ua;
            *(uint4*)&Bs[buf ^ 1][sr][sk] = uw;
            __syncthreads();
        }
    }

    #pragma unroll
    for (int mm = 0; mm < 2; mm++) {
        #pragma unroll
        for (int nn = 0; nn < 2; nn++) {
            int M = m0 + wm + mm * 16;
            int N = n0 + wn + nn * 8 + qd;
            float b0 = bias ? bias[N] : 0.f;
            float b1 = bias ? bias[N + 1] : 0.f;
            float c0 = acc[mm][nn][0] + b0, c1 = acc[mm][nn][1] + b1;
            float c2 = acc[mm][nn][2] + b0, c3 = acc[mm][nn][3] + b1;
            if (MODE == 0) {
                __half2 h01 = __floats2half2_rn(c0, c1);
                __half2 h23 = __floats2half2_rn(c2, c3);
                *(u32*)(outh + (size_t)(M + g) * ldo + N)     = *(u32*)&h01;
                *(u32*)(outh + (size_t)(M + g + 8) * ldo + N) = *(u32*)&h23;
            } else if (MODE == 1) {
                // rows M+g, M+g+8 are seq positions; cols N, N+1 are d dims
                int bb = M >> 9;
                int s = (M & 511) + g;
                int h = N >> 6, dd = N & 63;
                __half* r0 = outh + ((size_t)((bb * Hd + h) * HDd + dd)) * Sd;
                __half* r1 = r0 + Sd;
                r0[s] = __float2half(c0); r1[s] = __float2half(c1);
                r0[s + 8] = __float2half(c2); r1[s + 8] = __float2half(c3);
            } else {
                float2 o0 = { c0, c1 }, o1 = { c2, c3 };
                *(float2*)(outf + (size_t)(M + g) * ldo + N)     = o0;
                *(float2*)(outf + (size_t)(M + g + 8) * ldo + N) = o1;
            }
        }
    }
}

// z=0: q, z=1: k (f16 row-major), z=2: v (f16 transposed per (b,h))
__global__ __launch_bounds__(256) void proj_mma_kernel(const float* __restrict__ bv) {
    int z = blockIdx.z;
    int m0 = blockIdx.y * 64, n0 = blockIdx.x * 64;
    if (z == 0)
        mma_tile<0>(g_xq16, Dd, g_Wqh, Dd, g_bq, g_qth, nullptr, m0, n0, Dd);
    else if (z == 1)
        mma_tile<0>(g_xk16, Dd, g_Wkh, Dd, g_bk, g_kth, nullptr, m0, n0, Dd);
    else
        mma_tile<1>(g_xv16, Dd, g_Wvh, Dd, bv, g_v16T, nullptr, m0, n0, 0);
}

// ctx = att16 @ v16T^T per (b,h): M=512, N=64, K=512
__global__ __launch_bounds__(256) void ctx_mma_kernel() {
    int bh = blockIdx.y;
    int b = bh >> 3, h = bh & 7;
    const __half* A  = g_att16 + (size_t)bh * Sd * Sd;
    const __half* BT = g_v16T + (size_t)bh * HDd * Sd;
    __half* outh = g_ctx16 + (size_t)(b * Sd) * Dd + h * HDd;
    mma_tile<0>(A, Sd, BT, Sd, nullptr, outh, nullptr, blockIdx.x * 64, 0, Dd);
}

// out = ctx16 @ Wo^T + bo, fp32 out
__global__ __launch_bounds__(256) void out_mma_kernel(const float* __restrict__ bo,
                                                      float* __restrict__ out) {
    mma_tile<2>(g_ctx16, Dd, g_Woh, Dd, bo, nullptr, out,
                blockIdx.y * 64, blockIdx.x * 64, Dd);
}

// ---------------- scores + softmax, 512 thr = 16 warps = 16 q rows ----------------
__global__ __launch_bounds__(512, 2) void scores_kernel(const float* __restrict__ av,
                                                        float* __restrict__ attn_out) {
    __shared__ __half  ks[32][72];
    __shared__ __half  qs[16][72];
    __shared__ __half2 avh[32];

    int b = blockIdx.z, h = blockIdx.y;
    int q0 = blockIdx.x * 16;
    int tid = threadIdx.x;
    int w = tid >> 5, ln = tid & 31;

    if (tid < 32) avh[tid] = __floats2half2_rn(av[2 * tid], av[2 * tid + 1]);
    {
        int row = tid >> 5, c = (tid & 31) << 1;
        *(u32*)&qs[row][c] =
            *(const u32*)(g_qth + ((size_t)(b * Sd + q0 + row)) * Dd + h * HDd + c);
    }
    __syncthreads();

    float s[16];

    for (int c0 = 0; c0 < Sd; c0 += 32) {
        {
            int row = tid >> 4, c = (tid & 15) << 2;
            *(uint2*)&ks[row][c] =
                *(const uint2*)(g_kth + ((size_t)(b * Sd + c0 + row)) * Dd + h * HDd + c);
        }
        __syncthreads();

        float acc = 0.f;
        #pragma unroll
        for (int jc = 0; jc < 8; jc++) {
            uint4 kk = *(const uint4*)&ks[ln][jc << 3];
            uint4 qq = *(const uint4*)&qs[w][jc << 3];
            uint4 aa = *(const uint4*)&avh[jc << 2];
            u32 acch = 0;
            tchain(qq.x, kk.x, aa.x, acch);
            tchain(qq.y, kk.y, aa.y, acch);
            tchain(qq.z, kk.z, aa.z, acch);
            tchain(qq.w, kk.w, aa.w, acch);
            float lo, hi; h2f2(acch, lo, hi);
            acc += lo; acc += hi;
        }
        s[c0 >> 5] = acc;
        __syncthreads();
    }

    // softmax over the 512 scores of q row w
    float mx = -1e30f;
    #pragma unroll
    for (int j = 0; j < 16; j++) mx = fmaxf(mx, s[j]);
    #pragma unroll
    for (int o = 16; o > 0; o >>= 1) mx = fmaxf(mx, __shfl_xor_sync(0xffffffffu, mx, o));
    float sum = 0.f;
    #pragma unroll
    for (int j = 0; j < 16; j++) { s[j] = __expf(s[j] - mx); sum += s[j]; }
    #pragma unroll
    for (int o = 16; o > 0; o >>= 1) sum += __shfl_xor_sync(0xffffffffu, sum, o);
    float inv = 1.f / sum;

    size_t rowoff = (((size_t)(b * Hd + h) * Sd) + q0 + w) * Sd;
    float* arow = attn_out + rowoff;
    __half* arow16 = g_att16 + rowoff;
    #pragma unroll
    for (int j = 0; j < 16; j++) {
        float a = s[j] * inv;
        arow[(j << 5) + ln] = a;
        arow16[(j << 5) + ln] = __float2half(a);
    }
}

// ---------------- launch ----------------
extern "C" void kernel_launch(void* const* d_in, const int* in_sizes, int n_in,
                              void* d_out, int out_size) {
    const float* query = (const float*)d_in[0];
    const float* key_  = (const float*)d_in[1];
    const float* value = (const float*)d_in[2];
    const float* Wq    = (const float*)d_in[3];
    const float* bq    = (const float*)d_in[4];
    const float* Wk    = (const float*)d_in[5];
    const float* bk    = (const float*)d_in[6];
    const float* Wv    = (const float*)d_in[7];
    const float* bv    = (const float*)d_in[8];
    const float* Wo    = (const float*)d_in[9];
    const float* bo    = (const float*)d_in[10];
    const float* Aq    = (const float*)d_in[11];
    const float* Ak    = (const float*)d_in[12];
    const float* av    = (const float*)d_in[13];

    float* out      = (float*)d_out;                  // [B,S,D]
    float* attn_out = out + (size_t)Bd * Sd * Dd;     // [B,H,S,S]

    cvt_kernel<<<768, 256>>>(query, key_, value);
    fold_kernel<<<dim3(512, 8, 2), 64>>>(Wq, Aq, bq, Wk, Ak, bk);
    wcvt_kernel<<<dim3(16, 16, 2), 256>>>(Wv, Wo);
    proj_mma_kernel<<<dim3(8, 16, 3), 256>>>(bv);
    scores_kernel<<<dim3(32, Hd, Bd), 512>>>(av, attn_out);
    ctx_mma_kernel<<<dim3(8, 16), 256>>>();
    out_mma_kernel<<<dim3(8, 16), 256>>>(bo, out);
}

// round 7
// speedup vs baseline: 2.4160x; 1.2191x over previous
#include <cuda_runtime.h>
#include <cuda_fp16.h>

#define Dd  512
#define Sd  512
#define Bd  2
#define Hd  8
#define HDd 64

typedef unsigned long long u64;
typedef unsigned int u32;

// ---------------- scratch (device globals) ----------------
__device__ __half g_Wqh[Dd * Dd];       // folded Wq@Aq, transposed [n][k], f16
__device__ __half g_Wkh[Dd * Dd];       // folded Wk@Ak, transposed [n][k], f16
__device__ __half g_Wvh[Dd * Dd];       // Wv transposed [n][k], f16
__device__ __half g_Woh[Dd * Dd];       // Wo transposed [n][k], f16
__device__ float  g_bq[Dd];
__device__ float  g_bk[Dd];
__device__ __half g_xq16[Bd * Sd * Dd];
__device__ __half g_xk16[Bd * Sd * Dd];
__device__ __half g_xv16[Bd * Sd * Dd];
__device__ __half g_qth[Bd * Sd * Dd];  // q_term f16, row-major
__device__ __half g_kth[Bd * Sd * Dd];  // k_term f16
__device__ __half g_v16T[Bd * Hd * HDd * Sd]; // v, per (b,h) transposed [d][s]
__device__ __half g_att16[Bd * Hd * Sd * Sd]; // attn weights f16
__device__ __half g_ctx16[Bd * Sd * Dd];      // ctx f16, row-major

// ---------------- asm helpers ----------------
__device__ __forceinline__ void h2f2(u32 h, float& lo, float& hi) {
    asm("{ .reg .b16 l, h;\n\t mov.b32 {l, h}, %2;\n\t"
        " cvt.f32.f16 %0, l;\n\t cvt.f32.f16 %1, h; }"
        : "=f"(lo), "=f"(hi) : "r"(h));
}
__device__ __forceinline__ void tchain(u32 q2, u32 k2, u32 a2, u32& acch) {
    u32 x2, t2;
    asm("add.rn.f16x2 %0, %1, %2;" : "=r"(x2) : "r"(q2), "r"(k2));
    asm("tanh.approx.f16x2 %0, %1;" : "=r"(t2) : "r"(x2));
    asm("fma.rn.f16x2 %0, %1, %2, %0;" : "+r"(acch) : "r"(t2), "r"(a2));
}
__device__ __forceinline__ void mma16816(float* d, const u32* a, const u32* b) {
    asm volatile(
        "mma.sync.aligned.m16n8k16.row.col.f32.f16.f16.f32 "
        "{%0,%1,%2,%3}, {%4,%5,%6,%7}, {%8,%9}, {%0,%1,%2,%3};"
        : "+f"(d[0]), "+f"(d[1]), "+f"(d[2]), "+f"(d[3])
        : "r"(a[0]), "r"(a[1]), "r"(a[2]), "r"(a[3]), "r"(b[0]), "r"(b[1]));
}
__device__ __forceinline__ void ldsm4(u32& r0, u32& r1, u32& r2, u32& r3, u32 addr) {
    asm volatile("ldmatrix.sync.aligned.m8n8.x4.shared.b16 {%0,%1,%2,%3}, [%4];"
                 : "=r"(r0), "=r"(r1), "=r"(r2), "=r"(r3) : "r"(addr));
}
__device__ __forceinline__ void cp16(u32 dst, const void* src) {
    asm volatile("cp.async.cg.shared.global [%0], [%1], 16;" :: "r"(dst), "l"(src));
}

// ---------------- prep: cvt q/k/v fp32->f16  +  Wv/Wo transpose->f16 ----------
__global__ __launch_bounds__(256) void prep_kernel(const float* __restrict__ q,
                                                   const float* __restrict__ k,
                                                   const float* __restrict__ v,
                                                   const float* __restrict__ Wv,
                                                   const float* __restrict__ Wo) {
    __shared__ float Ts[32][33];
    int bx = blockIdx.x, tid = threadIdx.x;
    if (bx < 768) {
        int t = bx * 256 + tid;
        int sel = t >> 16;
        const float* src = (sel == 0) ? q : (sel == 1) ? k : v;
        __half* dst = (sel == 0) ? g_xq16 : (sel == 1) ? g_xk16 : g_xv16;
        int base = (t & 65535) * 8;
        float4 a = *(const float4*)(src + base);
        float4 b = *(const float4*)(src + base + 4);
        __half2 h0 = __floats2half2_rn(a.x, a.y), h1 = __floats2half2_rn(a.z, a.w);
        __half2 h2 = __floats2half2_rn(b.x, b.y), h3 = __floats2half2_rn(b.z, b.w);
        uint4 u;
        u.x = *(u32*)&h0; u.y = *(u32*)&h1; u.z = *(u32*)&h2; u.w = *(u32*)&h3;
        *(uint4*)(dst + base) = u;
    } else {
        int idx = bx - 768;
        int z = idx >> 8, rem = idx & 255;
        const float* src = z ? Wo : Wv;
        __half* dst = z ? g_Woh : g_Wvh;
        int k0 = (rem >> 4) * 32, n0 = (rem & 15) * 32;
        int r = tid >> 3, c4 = (tid & 7) << 2;
        float4 w = *(const float4*)(src + (size_t)(k0 + r) * Dd + n0 + c4);
        Ts[r][c4 + 0] = w.x; Ts[r][c4 + 1] = w.y;
        Ts[r][c4 + 2] = w.z; Ts[r][c4 + 3] = w.w;
        __syncthreads();
        __half2 h0 = __floats2half2_rn(Ts[c4 + 0][r], Ts[c4 + 1][r]);
        __half2 h1 = __floats2half2_rn(Ts[c4 + 2][r], Ts[c4 + 3][r]);
        uint2 u; u.x = *(u32*)&h0; u.y = *(u32*)&h1;
        *(uint2*)(dst + (size_t)(n0 + r) * Dd + k0 + c4) = u;
    }
}

// ---------------- fold: Wd[n][k] = sum_j W[k, h*64+j]*A[j, n&63], f16 transposed
// grid (8 mtile, 8 head, 2 sel), 256 threads. A staged ONCE per block.
__global__ __launch_bounds__(256) void fold_kernel(const float* __restrict__ Wq,
                                                   const float* __restrict__ Aq,
                                                   const float* __restrict__ bqi,
                                                   const float* __restrict__ Wk,
                                                   const float* __restrict__ Ak,
                                                   const float* __restrict__ bki) {
    __shared__ float At[64][68];   // A[j][c]
    __shared__ float Wt[64][65];   // W transposed: Wt[j][r], r in 0..63 (+1 pad)
    int sel = blockIdx.z, h = blockIdx.y;
    int R0 = blockIdx.x * 64;
    const float* W = sel ? Wk : Wq;
    const float* A = sel ? Ak : Aq;
    const float* bs = sel ? bki : bqi;
    __half* Wd = sel ? g_Wkh : g_Wqh;
    float* bd = sel ? g_bk : g_bq;
    int tid = threadIdx.x;

    {   // stage A: thread j = tid>>2, cols (tid&3)*16 .. +15
        int j = tid >> 2, c0 = (tid & 3) << 4;
        #pragma unroll
        for (int i = 0; i < 4; i++) {
            float4 a = *(const float4*)(A + j * 64 + c0 + i * 4);
            At[j][c0 + i * 4 + 0] = a.x; At[j][c0 + i * 4 + 1] = a.y;
            At[j][c0 + i * 4 + 2] = a.z; At[j][c0 + i * 4 + 3] = a.w;
        }
        // stage W transposed: thread r = tid>>2, j0 = (tid&3)*16
        int r = tid >> 2, j0 = (tid & 3) << 4;
        #pragma unroll
        for (int i = 0; i < 4; i++) {
            float4 w = *(const float4*)(W + (size_t)(R0 + r) * Dd + h * 64 + j0 + i * 4);
            Wt[j0 + i * 4 + 0][r] = w.x; Wt[j0 + i * 4 + 1][r] = w.y;
            Wt[j0 + i * 4 + 2][r] = w.z; Wt[j0 + i * 4 + 3][r] = w.w;
        }
    }
    __syncthreads();

    int w = tid >> 5, l = tid & 31;
    int c0 = w * 8;
    float acc0[8] = {}, acc1[8] = {};
    #pragma unroll 8
    for (int j = 0; j < 64; j++) {
        float w0 = Wt[j][l], w1 = Wt[j][l + 32];
        float4 a0 = *(const float4*)&At[j][c0];
        float4 a1 = *(const float4*)&At[j][c0 + 4];
        acc0[0] += w0 * a0.x; acc0[1] += w0 * a0.y; acc0[2] += w0 * a0.z; acc0[3] += w0 * a0.w;
        acc0[4] += w0 * a1.x; acc0[5] += w0 * a1.y; acc0[6] += w0 * a1.z; acc0[7] += w0 * a1.w;
        acc1[0] += w1 * a0.x; acc1[1] += w1 * a0.y; acc1[2] += w1 * a0.z; acc1[3] += w1 * a0.w;
        acc1[4] += w1 * a1.x; acc1[5] += w1 * a1.y; acc1[6] += w1 * a1.z; acc1[7] += w1 * a1.w;
    }
    #pragma unroll
    for (int i = 0; i < 8; i++) {
        int c = c0 + i;
        Wd[(size_t)(h * 64 + c) * Dd + R0 + l]      = __float2half(acc0[i]);
        Wd[(size_t)(h * 64 + c) * Dd + R0 + 32 + l] = __float2half(acc1[i]);
    }

    if (blockIdx.x == 0 && tid < 64) {
        float bacc = 0.f;
        #pragma unroll 16
        for (int j = 0; j < 64; j++) bacc += bs[h * 64 + j] * At[j][tid];
        bd[h * 64 + tid] = bacc;
    }
}

// ---------------- HMMA tile body v2: 64m x 64n, K=512, cp.async + ldmatrix ----
// X row-major [m][k] (lda), BT row-major [n][k] (ldb).
// MODE 0: f16 out row-major + bias; MODE 1: v16T transposed; MODE 2: f32 out + bias
template <int MODE>
__device__ __forceinline__ void mma_tile(const __half* __restrict__ X, int lda,
                                         const __half* __restrict__ BT, int ldb,
                                         const float* __restrict__ bias,
                                         __half* __restrict__ outh,
                                         float* __restrict__ outf,
                                         int m0, int n0, int ldo) {
    __shared__ __half As[2][64][40];
    __shared__ __half Bs[2][64][40];
    int tid = threadIdx.x, wid = tid >> 5, lane = tid & 31;
    int wm = (wid & 1) * 32, wn = (wid >> 1) * 16;
    int g = lane >> 2, qd = (lane & 3) * 2;
    int sr = tid >> 2, sk = (tid & 3) * 8;
    int lrow = lane & 15, lcol = (lane >> 4) << 3;

    u32 abase = (u32)__cvta_generic_to_shared(&As[0][0][0]);
    u32 bbase = (u32)__cvta_generic_to_shared(&Bs[0][0][0]);
    const u32 BUFB = 64 * 40 * 2;   // bytes per buffer

    float acc[2][2][4] = {};

    const __half* xg = X + (size_t)(m0 + sr) * lda + sk;
    const __half* bg = BT + (size_t)(n0 + sr) * ldb + sk;
    u32 adst = abase + (sr * 40 + sk) * 2;
    u32 bdst = bbase + (sr * 40 + sk) * 2;

    cp16(adst, xg);
    cp16(bdst, bg);
    asm volatile("cp.async.commit_group;");

    for (int ch = 0; ch < 16; ch++) {
        int buf = ch & 1;
        asm volatile("cp.async.wait_group 0;");
        __syncthreads();
        if (ch < 15) {
            int k0 = (ch + 1) * 32;
            u32 nb = (u32)(buf ^ 1) * BUFB;
            cp16(adst + nb, xg + k0);
            cp16(bdst + nb, bg + k0);
            asm volatile("cp.async.commit_group;");
        }
        u32 abuf = abase + (u32)buf * BUFB;
        u32 bbuf = bbase + (u32)buf * BUFB;
        #pragma unroll
        for (int ks = 0; ks < 32; ks += 16) {
            u32 a[2][4], b[2][2];
            ldsm4(a[0][0], a[0][1], a[0][2], a[0][3],
                  abuf + ((wm + lrow) * 40 + ks + lcol) * 2);
            ldsm4(a[1][0], a[1][1], a[1][2], a[1][3],
                  abuf + ((wm + 16 + lrow) * 40 + ks + lcol) * 2);
            u32 r0, r1, r2, r3;
            ldsm4(r0, r1, r2, r3,
                  bbuf + ((wn + lrow) * 40 + ks + lcol) * 2);
            b[0][0] = r0; b[0][1] = r2; b[1][0] = r1; b[1][1] = r3;
            mma16816(acc[0][0], a[0], b[0]); mma16816(acc[0][1], a[0], b[1]);
            mma16816(acc[1][0], a[1], b[0]); mma16816(acc[1][1], a[1], b[1]);
        }
    }

    #pragma unroll
    for (int mm = 0; mm < 2; mm++) {
        #pragma unroll
        for (int nn = 0; nn < 2; nn++) {
            int M = m0 + wm + mm * 16;
            int N = n0 + wn + nn * 8 + qd;
            float b0 = bias ? bias[N] : 0.f;
            float b1 = bias ? bias[N + 1] : 0.f;
            float c0 = acc[mm][nn][0] + b0, c1 = acc[mm][nn][1] + b1;
            float c2 = acc[mm][nn][2] + b0, c3 = acc[mm][nn][3] + b1;
            if (MODE == 0) {
                __half2 h01 = __floats2half2_rn(c0, c1);
                __half2 h23 = __floats2half2_rn(c2, c3);
                *(u32*)(outh + (size_t)(M + g) * ldo + N)     = *(u32*)&h01;
                *(u32*)(outh + (size_t)(M + g + 8) * ldo + N) = *(u32*)&h23;
            } else if (MODE == 1) {
                int bb = M >> 9;
                int s = (M & 511) + g;
                int h = N >> 6, dd = N & 63;
                __half* r0 = outh + ((size_t)((bb * Hd + h) * HDd + dd)) * Sd;
                __half* r1 = r0 + Sd;
                r0[s] = __float2half(c0); r1[s] = __float2half(c1);
                r0[s + 8] = __float2half(c2); r1[s + 8] = __float2half(c3);
            } else {
                float2 o0 = { c0, c1 }, o1 = { c2, c3 };
                *(float2*)(outf + (size_t)(M + g) * ldo + N)     = o0;
                *(float2*)(outf + (size_t)(M + g + 8) * ldo + N) = o1;
            }
        }
    }
}

// z=0: q, z=1: k (f16 row-major), z=2: v (f16 transposed per (b,h))
__global__ __launch_bounds__(256) void proj_mma_kernel(const float* __restrict__ bv) {
    int z = blockIdx.z;
    int m0 = blockIdx.y * 64, n0 = blockIdx.x * 64;
    if (z == 0)
        mma_tile<0>(g_xq16, Dd, g_Wqh, Dd, g_bq, g_qth, nullptr, m0, n0, Dd);
    else if (z == 1)
        mma_tile<0>(g_xk16, Dd, g_Wkh, Dd, g_bk, g_kth, nullptr, m0, n0, Dd);
    else
        mma_tile<1>(g_xv16, Dd, g_Wvh, Dd, bv, g_v16T, nullptr, m0, n0, 0);
}

__global__ __launch_bounds__(256) void ctx_mma_kernel() {
    int bh = blockIdx.y;
    int b = bh >> 3, h = bh & 7;
    const __half* A  = g_att16 + (size_t)bh * Sd * Sd;
    const __half* BT = g_v16T + (size_t)bh * HDd * Sd;
    __half* outh = g_ctx16 + (size_t)(b * Sd) * Dd + h * HDd;
    mma_tile<0>(A, Sd, BT, Sd, nullptr, outh, nullptr, blockIdx.x * 64, 0, Dd);
}

__global__ __launch_bounds__(256) void out_mma_kernel(const float* __restrict__ bo,
                                                      float* __restrict__ out) {
    mma_tile<2>(g_ctx16, Dd, g_Woh, Dd, bo, nullptr, out,
                blockIdx.y * 64, blockIdx.x * 64, Dd);
}

// ---------------- scores + softmax, 512 thr = 16 warps = 16 q rows ----------------
__global__ __launch_bounds__(512, 2) void scores_kernel(const float* __restrict__ av,
                                                        float* __restrict__ attn_out) {
    __shared__ __half  ks[32][72];
    __shared__ __half  qs[16][72];
    __shared__ __half2 avh[32];

    int b = blockIdx.z, h = blockIdx.y;
    int q0 = blockIdx.x * 16;
    int tid = threadIdx.x;
    int w = tid >> 5, ln = tid & 31;

    if (tid < 32) avh[tid] = __floats2half2_rn(av[2 * tid], av[2 * tid + 1]);
    {
        int row = tid >> 5, c = (tid & 31) << 1;
        *(u32*)&qs[row][c] =
            *(const u32*)(g_qth + ((size_t)(b * Sd + q0 + row)) * Dd + h * HDd + c);
    }
    __syncthreads();

    float s[16];

    for (int c0 = 0; c0 < Sd; c0 += 32) {
        {
            int row = tid >> 4, c = (tid & 15) << 2;
            *(uint2*)&ks[row][c] =
                *(const uint2*)(g_kth + ((size_t)(b * Sd + c0 + row)) * Dd + h * HDd + c);
        }
        __syncthreads();

        float acc = 0.f;
        #pragma unroll
        for (int jc = 0; jc < 8; jc++) {
            uint4 kk = *(const uint4*)&ks[ln][jc << 3];
            uint4 qq = *(const uint4*)&qs[w][jc << 3];
            uint4 aa = *(const uint4*)&avh[jc << 2];
            u32 acch = 0;
            tchain(qq.x, kk.x, aa.x, acch);
            tchain(qq.y, kk.y, aa.y, acch);
            tchain(qq.z, kk.z, aa.z, acch);
            tchain(qq.w, kk.w, aa.w, acch);
            float lo, hi; h2f2(acch, lo, hi);
            acc += lo; acc += hi;
        }
        s[c0 >> 5] = acc;
        __syncthreads();
    }

    float mx = -1e30f;
    #pragma unroll
    for (int j = 0; j < 16; j++) mx = fmaxf(mx, s[j]);
    #pragma unroll
    for (int o = 16; o > 0; o >>= 1) mx = fmaxf(mx, __shfl_xor_sync(0xffffffffu, mx, o));
    float sum = 0.f;
    #pragma unroll
    for (int j = 0; j < 16; j++) { s[j] = __expf(s[j] - mx); sum += s[j]; }
    #pragma unroll
    for (int o = 16; o > 0; o >>= 1) sum += __shfl_xor_sync(0xffffffffu, sum, o);
    float inv = 1.f / sum;

    size_t rowoff = (((size_t)(b * Hd + h) * Sd) + q0 + w) * Sd;
    float* arow = attn_out + rowoff;
    __half* arow16 = g_att16 + rowoff;
    #pragma unroll
    for (int j = 0; j < 16; j++) {
        float a = s[j] * inv;
        arow[(j << 5) + ln] = a;
        arow16[(j << 5) + ln] = __float2half(a);
    }
}

// ---------------- launch ----------------
extern "C" void kernel_launch(void* const* d_in, const int* in_sizes, int n_in,
                              void* d_out, int out_size) {
    const float* query = (const float*)d_in[0];
    const float* key_  = (const float*)d_in[1];
    const float* value = (const float*)d_in[2];
    const float* Wq    = (const float*)d_in[3];
    const float* bq    = (const float*)d_in[4];
    const float* Wk    = (const float*)d_in[5];
    const float* bk    = (const float*)d_in[6];
    const float* Wv    = (const float*)d_in[7];
    const float* bv    = (const float*)d_in[8];
    const float* Wo    = (const float*)d_in[9];
    const float* bo    = (const float*)d_in[10];
    const float* Aq    = (const float*)d_in[11];
    const float* Ak    = (const float*)d_in[12];
    const float* av    = (const float*)d_in[13];

    float* out      = (float*)d_out;                  // [B,S,D]
    float* attn_out = out + (size_t)Bd * Sd * Dd;     // [B,H,S,S]

    prep_kernel<<<1280, 256>>>(query, key_, value, Wv, Wo);
    fold_kernel<<<dim3(8, 8, 2), 256>>>(Wq, Aq, bq, Wk, Ak, bk);
    proj_mma_kernel<<<dim3(8, 16, 3), 256>>>(bv);
    scores_kernel<<<dim3(32, Hd, Bd), 512>>>(av, attn_out);
    ctx_mma_kernel<<<dim3(8, 16), 256>>>();
    out_mma_kernel<<<dim3(8, 16), 256>>>(bo, out);
}

// round 8
// speedup vs baseline: 2.6053x; 1.0784x over previous
#include <cuda_runtime.h>
#include <cuda_fp16.h>

#define Dd  512
#define Sd  512
#define Bd  2
#define Hd  8
#define HDd 64

typedef unsigned long long u64;
typedef unsigned int u32;

// ---------------- scratch (device globals) ----------------
__device__ __half g_Wqh[Dd * Dd];       // folded Wq@Aq, transposed [n][k], f16
__device__ __half g_Wkh[Dd * Dd];       // folded Wk@Ak, transposed [n][k], f16
__device__ __half g_Wvh[Dd * Dd];       // Wv transposed [n][k], f16
__device__ __half g_Woh[Dd * Dd];       // Wo transposed [n][k], f16
__device__ float  g_bq[Dd];
__device__ float  g_bk[Dd];
__device__ __half g_xq16[Bd * Sd * Dd];
__device__ __half g_xk16[Bd * Sd * Dd];
__device__ __half g_xv16[Bd * Sd * Dd];
__device__ __half g_qth[Bd * Sd * Dd];  // q_term f16, row-major
__device__ __half g_kth[Bd * Sd * Dd];  // k_term f16
__device__ __half g_v16T[Bd * Hd * HDd * Sd]; // v, per (b,h) transposed [d][s]
__device__ __half g_att16[Bd * Hd * Sd * Sd]; // attn weights f16
__device__ __half g_ctx16[Bd * Sd * Dd];      // ctx f16, row-major

// ---------------- asm helpers ----------------
__device__ __forceinline__ void h2f2(u32 h, float& lo, float& hi) {
    asm("{ .reg .b16 l, h;\n\t mov.b32 {l, h}, %2;\n\t"
        " cvt.f32.f16 %0, l;\n\t cvt.f32.f16 %1, h; }"
        : "=f"(lo), "=f"(hi) : "r"(h));
}
__device__ __forceinline__ void tchain(u32 q2, u32 k2, u32 a2, u32& acch) {
    u32 x2, t2;
    asm("add.rn.f16x2 %0, %1, %2;" : "=r"(x2) : "r"(q2), "r"(k2));
    asm("tanh.approx.f16x2 %0, %1;" : "=r"(t2) : "r"(x2));
    asm("fma.rn.f16x2 %0, %1, %2, %0;" : "+r"(acch) : "r"(t2), "r"(a2));
}
__device__ __forceinline__ void mma16816(float* d, const u32* a, const u32* b) {
    asm volatile(
        "mma.sync.aligned.m16n8k16.row.col.f32.f16.f16.f32 "
        "{%0,%1,%2,%3}, {%4,%5,%6,%7}, {%8,%9}, {%0,%1,%2,%3};"
        : "+f"(d[0]), "+f"(d[1]), "+f"(d[2]), "+f"(d[3])
        : "r"(a[0]), "r"(a[1]), "r"(a[2]), "r"(a[3]), "r"(b[0]), "r"(b[1]));
}
__device__ __forceinline__ void ldsm4(u32& r0, u32& r1, u32& r2, u32& r3, u32 addr) {
    asm volatile("ldmatrix.sync.aligned.m8n8.x4.shared.b16 {%0,%1,%2,%3}, [%4];"
                 : "=r"(r0), "=r"(r1), "=r"(r2), "=r"(r3) : "r"(addr));
}
__device__ __forceinline__ void cp16(u32 dst, const void* src) {
    asm volatile("cp.async.cg.shared.global [%0], [%1], 16;" :: "r"(dst), "l"(src));
}

// ---------------- fused prep + fold ----------------
// bx < 768:   cvt q/k/v fp32 -> f16
// bx < 1280:  Wv/Wo transpose -> f16
// bx >= 1280: fold Wq@Aq / Wk@Ak -> f16 transposed (+ bias fold)
__global__ __launch_bounds__(256) void prep_fold_kernel(
        const float* __restrict__ q, const float* __restrict__ k,
        const float* __restrict__ v,
        const float* __restrict__ Wv, const float* __restrict__ Wo,
        const float* __restrict__ Wq, const float* __restrict__ Aq,
        const float* __restrict__ bqi,
        const float* __restrict__ Wk, const float* __restrict__ Ak,
        const float* __restrict__ bki) {
    __shared__ float pool[8512];    // fold: At[64][68] + Wt[64][65]; prep: Ts[32][33]
    int bx = blockIdx.x, tid = threadIdx.x;

    if (bx < 768) {
        int t = bx * 256 + tid;
        int sel = t >> 16;
        const float* src = (sel == 0) ? q : (sel == 1) ? k : v;
        __half* dst = (sel == 0) ? g_xq16 : (sel == 1) ? g_xk16 : g_xv16;
        int base = (t & 65535) * 8;
        float4 a = *(const float4*)(src + base);
        float4 b = *(const float4*)(src + base + 4);
        __half2 h0 = __floats2half2_rn(a.x, a.y), h1 = __floats2half2_rn(a.z, a.w);
        __half2 h2 = __floats2half2_rn(b.x, b.y), h3 = __floats2half2_rn(b.z, b.w);
        uint4 u;
        u.x = *(u32*)&h0; u.y = *(u32*)&h1; u.z = *(u32*)&h2; u.w = *(u32*)&h3;
        *(uint4*)(dst + base) = u;
    } else if (bx < 1280) {
        float (*Ts)[33] = (float(*)[33])pool;
        int idx = bx - 768;
        int z = idx >> 8, rem = idx & 255;
        const float* src = z ? Wo : Wv;
        __half* dst = z ? g_Woh : g_Wvh;
        int k0 = (rem >> 4) * 32, n0 = (rem & 15) * 32;
        int r = tid >> 3, c4 = (tid & 7) << 2;
        float4 w = *(const float4*)(src + (size_t)(k0 + r) * Dd + n0 + c4);
        Ts[r][c4 + 0] = w.x; Ts[r][c4 + 1] = w.y;
        Ts[r][c4 + 2] = w.z; Ts[r][c4 + 3] = w.w;
        __syncthreads();
        __half2 h0 = __floats2half2_rn(Ts[c4 + 0][r], Ts[c4 + 1][r]);
        __half2 h1 = __floats2half2_rn(Ts[c4 + 2][r], Ts[c4 + 3][r]);
        uint2 u; u.x = *(u32*)&h0; u.y = *(u32*)&h1;
        *(uint2*)(dst + (size_t)(n0 + r) * Dd + k0 + c4) = u;
    } else {
        float (*At)[68] = (float(*)[68])pool;
        float (*Wt)[65] = (float(*)[65])(pool + 64 * 68);
        int idx = bx - 1280;             // 0..127
        int sel = idx >> 6, h = (idx >> 3) & 7, R0 = (idx & 7) * 64;
        const float* W = sel ? Wk : Wq;
        const float* A = sel ? Ak : Aq;
        const float* bs = sel ? bki : bqi;
        __half* Wd = sel ? g_Wkh : g_Wqh;
        float* bd = sel ? g_bk : g_bq;

        {
            int j = tid >> 2, c0 = (tid & 3) << 4;
            #pragma unroll
            for (int i = 0; i < 4; i++) {
                float4 a = *(const float4*)(A + j * 64 + c0 + i * 4);
                At[j][c0 + i * 4 + 0] = a.x; At[j][c0 + i * 4 + 1] = a.y;
                At[j][c0 + i * 4 + 2] = a.z; At[j][c0 + i * 4 + 3] = a.w;
            }
            int r = tid >> 2, j0 = (tid & 3) << 4;
            #pragma unroll
            for (int i = 0; i < 4; i++) {
                float4 w = *(const float4*)(W + (size_t)(R0 + r) * Dd + h * 64 + j0 + i * 4);
                Wt[j0 + i * 4 + 0][r] = w.x; Wt[j0 + i * 4 + 1][r] = w.y;
                Wt[j0 + i * 4 + 2][r] = w.z; Wt[j0 + i * 4 + 3][r] = w.w;
            }
        }
        __syncthreads();

        int w = tid >> 5, l = tid & 31;
        int c0 = w * 8;
        float acc0[8] = {}, acc1[8] = {};
        #pragma unroll 8
        for (int j = 0; j < 64; j++) {
            float w0 = Wt[j][l], w1 = Wt[j][l + 32];
            float4 a0 = *(const float4*)&At[j][c0];
            float4 a1 = *(const float4*)&At[j][c0 + 4];
            acc0[0] += w0 * a0.x; acc0[1] += w0 * a0.y; acc0[2] += w0 * a0.z; acc0[3] += w0 * a0.w;
            acc0[4] += w0 * a1.x; acc0[5] += w0 * a1.y; acc0[6] += w0 * a1.z; acc0[7] += w0 * a1.w;
            acc1[0] += w1 * a0.x; acc1[1] += w1 * a0.y; acc1[2] += w1 * a0.z; acc1[3] += w1 * a0.w;
            acc1[4] += w1 * a1.x; acc1[5] += w1 * a1.y; acc1[6] += w1 * a1.z; acc1[7] += w1 * a1.w;
        }
        #pragma unroll
        for (int i = 0; i < 8; i++) {
            int c = c0 + i;
            Wd[(size_t)(h * 64 + c) * Dd + R0 + l]      = __float2half(acc0[i]);
            Wd[(size_t)(h * 64 + c) * Dd + R0 + 32 + l] = __float2half(acc1[i]);
        }

        if (R0 == 0 && tid < 64) {
            float bacc = 0.f;
            #pragma unroll 16
            for (int j = 0; j < 64; j++) bacc += bs[h * 64 + j] * At[j][tid];
            bd[h * 64 + tid] = bacc;
        }
    }
}

// ---------------- HMMA tile body: 64m x 64n, K=512, cp.async + ldmatrix ----
template <int MODE>
__device__ __forceinline__ void mma_tile(const __half* __restrict__ X, int lda,
                                         const __half* __restrict__ BT, int ldb,
                                         const float* __restrict__ bias,
                                         __half* __restrict__ outh,
                                         float* __restrict__ outf,
                                         int m0, int n0, int ldo) {
    __shared__ __half As[2][64][40];
    __shared__ __half Bs[2][64][40];
    int tid = threadIdx.x, wid = tid >> 5, lane = tid & 31;
    int wm = (wid & 1) * 32, wn = (wid >> 1) * 16;
    int g = lane >> 2, qd = (lane & 3) * 2;
    int sr = tid >> 2, sk = (tid & 3) * 8;
    int lrow = lane & 15, lcol = (lane >> 4) << 3;

    u32 abase = (u32)__cvta_generic_to_shared(&As[0][0][0]);
    u32 bbase = (u32)__cvta_generic_to_shared(&Bs[0][0][0]);
    const u32 BUFB = 64 * 40 * 2;

    float acc[2][2][4] = {};

    const __half* xg = X + (size_t)(m0 + sr) * lda + sk;
    const __half* bg = BT + (size_t)(n0 + sr) * ldb + sk;
    u32 adst = abase + (sr * 40 + sk) * 2;
    u32 bdst = bbase + (sr * 40 + sk) * 2;

    cp16(adst, xg);
    cp16(bdst, bg);
    asm volatile("cp.async.commit_group;");

    for (int ch = 0; ch < 16; ch++) {
        int buf = ch & 1;
        asm volatile("cp.async.wait_group 0;");
        __syncthreads();
        if (ch < 15) {
            int k0 = (ch + 1) * 32;
            u32 nb = (u32)(buf ^ 1) * BUFB;
            cp16(adst + nb, xg + k0);
            cp16(bdst + nb, bg + k0);
            asm volatile("cp.async.commit_group;");
        }
        u32 abuf = abase + (u32)buf * BUFB;
        u32 bbuf = bbase + (u32)buf * BUFB;
        #pragma unroll
        for (int ks = 0; ks < 32; ks += 16) {
            u32 a[2][4], b[2][2];
            ldsm4(a[0][0], a[0][1], a[0][2], a[0][3],
                  abuf + ((wm + lrow) * 40 + ks + lcol) * 2);
            ldsm4(a[1][0], a[1][1], a[1][2], a[1][3],
                  abuf + ((wm + 16 + lrow) * 40 + ks + lcol) * 2);
            u32 r0, r1, r2, r3;
            ldsm4(r0, r1, r2, r3,
                  bbuf + ((wn + lrow) * 40 + ks + lcol) * 2);
            b[0][0] = r0; b[0][1] = r2; b[1][0] = r1; b[1][1] = r3;
            mma16816(acc[0][0], a[0], b[0]); mma16816(acc[0][1], a[0], b[1]);
            mma16816(acc[1][0], a[1], b[0]); mma16816(acc[1][1], a[1], b[1]);
        }
    }

    #pragma unroll
    for (int mm = 0; mm < 2; mm++) {
        #pragma unroll
        for (int nn = 0; nn < 2; nn++) {
            int M = m0 + wm + mm * 16;
            int N = n0 + wn + nn * 8 + qd;
            float b0 = bias ? bias[N] : 0.f;
            float b1 = bias ? bias[N + 1] : 0.f;
            float c0 = acc[mm][nn][0] + b0, c1 = acc[mm][nn][1] + b1;
            float c2 = acc[mm][nn][2] + b0, c3 = acc[mm][nn][3] + b1;
            if (MODE == 0) {
                __half2 h01 = __floats2half2_rn(c0, c1);
                __half2 h23 = __floats2half2_rn(c2, c3);
                *(u32*)(outh + (size_t)(M + g) * ldo + N)     = *(u32*)&h01;
                *(u32*)(outh + (size_t)(M + g + 8) * ldo + N) = *(u32*)&h23;
            } else if (MODE == 1) {
                int bb = M >> 9;
                int s = (M & 511) + g;
                int h = N >> 6, dd = N & 63;
                __half* r0 = outh + ((size_t)((bb * Hd + h) * HDd + dd)) * Sd;
                __half* r1 = r0 + Sd;
                r0[s] = __float2half(c0); r1[s] = __float2half(c1);
                r0[s + 8] = __float2half(c2); r1[s + 8] = __float2half(c3);
            } else {
                float2 o0 = { c0, c1 }, o1 = { c2, c3 };
                *(float2*)(outf + (size_t)(M + g) * ldo + N)     = o0;
                *(float2*)(outf + (size_t)(M + g + 8) * ldo + N) = o1;
            }
        }
    }
}

__global__ __launch_bounds__(256) void proj_mma_kernel(const float* __restrict__ bv) {
    int z = blockIdx.z;
    int m0 = blockIdx.y * 64, n0 = blockIdx.x * 64;
    if (z == 0)
        mma_tile<0>(g_xq16, Dd, g_Wqh, Dd, g_bq, g_qth, nullptr, m0, n0, Dd);
    else if (z == 1)
        mma_tile<0>(g_xk16, Dd, g_Wkh, Dd, g_bk, g_kth, nullptr, m0, n0, Dd);
    else
        mma_tile<1>(g_xv16, Dd, g_Wvh, Dd, bv, g_v16T, nullptr, m0, n0, 0);
}

__global__ __launch_bounds__(256) void ctx_mma_kernel() {
    int bh = blockIdx.y;
    int b = bh >> 3, h = bh & 7;
    const __half* A  = g_att16 + (size_t)bh * Sd * Sd;
    const __half* BT = g_v16T + (size_t)bh * HDd * Sd;
    __half* outh = g_ctx16 + (size_t)(b * Sd) * Dd + h * HDd;
    mma_tile<0>(A, Sd, BT, Sd, nullptr, outh, nullptr, blockIdx.x * 64, 0, Dd);
}

__global__ __launch_bounds__(256) void out_mma_kernel(const float* __restrict__ bo,
                                                      float* __restrict__ out) {
    mma_tile<2>(g_ctx16, Dd, g_Woh, Dd, bo, nullptr, out,
                blockIdx.y * 64, blockIdx.x * 64, Dd);
}

// ---------------- scores v2: 512 thr = 16 warps = 16 q rows ----------------
// 128-k chunks (4 total), 4 k per lane, XOR-swizzled k tile (conflict-free).
__global__ __launch_bounds__(512, 2) void scores_kernel(const float* __restrict__ av,
                                                        float* __restrict__ attn_out) {
    __shared__ uint4 ks4[128][8];   // 16 KB, col ^ (row&7) swizzle
    __shared__ uint4 qs4[16][8];    // 2 KB
    __shared__ uint4 avh4[8];

    int b = blockIdx.z, h = blockIdx.y;
    int q0 = blockIdx.x * 16;
    int tid = threadIdx.x;
    int w = tid >> 5, ln = tid & 31;
    int swl = ln & 7;

    if (tid < 128) {
        int row = tid >> 3, c4 = tid & 7;
        qs4[row][c4] =
            *(const uint4*)(g_qth + ((size_t)(b * Sd + q0 + row)) * Dd + h * HDd + c4 * 8);
    } else if (tid < 160) {
        int i = tid - 128;
        __half2 hh = __floats2half2_rn(av[2 * i], av[2 * i + 1]);
        ((u32*)avh4)[i] = *(u32*)&hh;
    }

    float s[4][4];

    for (int ch = 0; ch < 4; ch++) {
        int c0 = ch * 128;
        #pragma unroll
        for (int i = 0; i < 2; i++) {
            int t = tid + i * 512;
            int row = t >> 3, c4 = t & 7;
            ks4[row][c4 ^ (row & 7)] =
                *(const uint4*)(g_kth + ((size_t)(b * Sd + c0 + row)) * Dd + h * HDd + c4 * 8);
        }
        __syncthreads();

        float sa0 = 0.f, sa1 = 0.f, sa2 = 0.f, sa3 = 0.f;
        #pragma unroll
        for (int j = 0; j < 8; j++) {
            uint4 qq = qs4[w][j];
            uint4 aa = avh4[j];
            int sc = j ^ swl;
            uint4 k0 = ks4[ln][sc];
            uint4 k1 = ks4[32 + ln][sc];
            uint4 k2 = ks4[64 + ln][sc];
            uint4 k3 = ks4[96 + ln][sc];
            u32 a0 = 0, a1 = 0, a2 = 0, a3 = 0;
            tchain(qq.x, k0.x, aa.x, a0); tchain(qq.y, k0.y, aa.y, a0);
            tchain(qq.z, k0.z, aa.z, a0); tchain(qq.w, k0.w, aa.w, a0);
            tchain(qq.x, k1.x, aa.x, a1); tchain(qq.y, k1.y, aa.y, a1);
            tchain(qq.z, k1.z, aa.z, a1); tchain(qq.w, k1.w, aa.w, a1);
            tchain(qq.x, k2.x, aa.x, a2); tchain(qq.y, k2.y, aa.y, a2);
            tchain(qq.z, k2.z, aa.z, a2); tchain(qq.w, k2.w, aa.w, a2);
            tchain(qq.x, k3.x, aa.x, a3); tchain(qq.y, k3.y, aa.y, a3);
            tchain(qq.z, k3.z, aa.z, a3); tchain(qq.w, k3.w, aa.w, a3);
            float lo, hi;
            h2f2(a0, lo, hi); sa0 += lo + hi;
            h2f2(a1, lo, hi); sa1 += lo + hi;
            h2f2(a2, lo, hi); sa2 += lo + hi;
            h2f2(a3, lo, hi); sa3 += lo + hi;
        }
        s[ch][0] = sa0; s[ch][1] = sa1; s[ch][2] = sa2; s[ch][3] = sa3;
        __syncthreads();
    }

    // softmax over 16 regs; k = ch*128 + m*32 + ln
    float mx = -1e30f;
    #pragma unroll
    for (int ch = 0; ch < 4; ch++)
        #pragma unroll
        for (int m = 0; m < 4; m++) mx = fmaxf(mx, s[ch][m]);
    #pragma unroll
    for (int o = 16; o > 0; o >>= 1) mx = fmaxf(mx, __shfl_xor_sync(0xffffffffu, mx, o));
    float sum = 0.f;
    #pragma unroll
    for (int ch = 0; ch < 4; ch++)
        #pragma unroll
        for (int m = 0; m < 4; m++) { s[ch][m] = __expf(s[ch][m] - mx); sum += s[ch][m]; }
    #pragma unroll
    for (int o = 16; o > 0; o >>= 1) sum += __shfl_xor_sync(0xffffffffu, sum, o);
    float inv = 1.f / sum;

    size_t rowoff = (((size_t)(b * Hd + h) * Sd) + q0 + w) * Sd;
    float* arow = attn_out + rowoff;
    __half* arow16 = g_att16 + rowoff;
    #pragma unroll
    for (int ch = 0; ch < 4; ch++)
        #pragma unroll
        for (int m = 0; m < 4; m++) {
            float a = s[ch][m] * inv;
            int kk = ch * 128 + m * 32 + ln;
            arow[kk] = a;
            arow16[kk] = __float2half(a);
        }
}

// ---------------- launch ----------------
extern "C" void kernel_launch(void* const* d_in, const int* in_sizes, int n_in,
                              void* d_out, int out_size) {
    const float* query = (const float*)d_in[0];
    const float* key_  = (const float*)d_in[1];
    const float* value = (const float*)d_in[2];
    const float* Wq    = (const float*)d_in[3];
    const float* bq    = (const float*)d_in[4];
    const float* Wk    = (const float*)d_in[5];
    const float* bk    = (const float*)d_in[6];
    const float* Wv    = (const float*)d_in[7];
    const float* bv    = (const float*)d_in[8];
    const float* Wo    = (const float*)d_in[9];
    const float* bo    = (const float*)d_in[10];
    const float* Aq    = (const float*)d_in[11];
    const float* Ak    = (const float*)d_in[12];
    const float* av    = (const float*)d_in[13];

    float* out      = (float*)d_out;                  // [B,S,D]
    float* attn_out = out + (size_t)Bd * Sd * Dd;     // [B,H,S,S]

    prep_fold_kernel<<<1408, 256>>>(query, key_, value, Wv, Wo,
                                    Wq, Aq, bq, Wk, Ak, bk);
    proj_mma_kernel<<<dim3(8, 16, 3), 256>>>(bv);
    scores_kernel<<<dim3(32, Hd, Bd), 512>>>(av, attn_out);
    ctx_mma_kernel<<<dim3(8, 16), 256>>>();
    out_mma_kernel<<<dim3(8, 16), 256>>>(bo, out);
}

// round 9
// speedup vs baseline: 2.6613x; 1.0215x over previous
#include <cuda_runtime.h>
#include <cuda_fp16.h>

#define Dd  512
#define Sd  512
#define Bd  2
#define Hd  8
#define HDd 64

typedef unsigned long long u64;
typedef unsigned int u32;

// ---------------- scratch (device globals) ----------------
__device__ __half g_Wqh[Dd * Dd];       // folded Wq@Aq, transposed [n][k], f16
__device__ __half g_Wkh[Dd * Dd];       // folded Wk@Ak, transposed [n][k], f16
__device__ __half g_Wvh[Dd * Dd];       // Wv transposed [n][k], f16
__device__ __half g_Woh[Dd * Dd];       // Wo transposed [n][k], f16
__device__ float  g_bq[Dd];
__device__ float  g_bk[Dd];
__device__ __half g_xq16[Bd * Sd * Dd];
__device__ __half g_xk16[Bd * Sd * Dd];
__device__ __half g_xv16[Bd * Sd * Dd];
__device__ __half g_qth[Bd * Sd * Dd];  // q_term f16, row-major
__device__ __half g_kth[Bd * Sd * Dd];  // k_term f16
__device__ __half g_v16T[Bd * Hd * HDd * Sd]; // v, per (b,h) transposed [d][s]
__device__ __half g_ctx16[Bd * Sd * Dd];      // ctx f16, row-major

// ---------------- asm helpers ----------------
__device__ __forceinline__ void h2f2(u32 h, float& lo, float& hi) {
    asm("{ .reg .b16 l, h;\n\t mov.b32 {l, h}, %2;\n\t"
        " cvt.f32.f16 %0, l;\n\t cvt.f32.f16 %1, h; }"
        : "=f"(lo), "=f"(hi) : "r"(h));
}
__device__ __forceinline__ void tchain(u32 q2, u32 k2, u32 a2, u32& acch) {
    u32 x2, t2;
    asm("add.rn.f16x2 %0, %1, %2;" : "=r"(x2) : "r"(q2), "r"(k2));
    asm("tanh.approx.f16x2 %0, %1;" : "=r"(t2) : "r"(x2));
    asm("fma.rn.f16x2 %0, %1, %2, %0;" : "+r"(acch) : "r"(t2), "r"(a2));
}
__device__ __forceinline__ void mma16816(float* d, const u32* a, const u32* b) {
    asm volatile(
        "mma.sync.aligned.m16n8k16.row.col.f32.f16.f16.f32 "
        "{%0,%1,%2,%3}, {%4,%5,%6,%7}, {%8,%9}, {%0,%1,%2,%3};"
        : "+f"(d[0]), "+f"(d[1]), "+f"(d[2]), "+f"(d[3])
        : "r"(a[0]), "r"(a[1]), "r"(a[2]), "r"(a[3]), "r"(b[0]), "r"(b[1]));
}
__device__ __forceinline__ void ldsm4(u32& r0, u32& r1, u32& r2, u32& r3, u32 addr) {
    asm volatile("ldmatrix.sync.aligned.m8n8.x4.shared.b16 {%0,%1,%2,%3}, [%4];"
                 : "=r"(r0), "=r"(r1), "=r"(r2), "=r"(r3) : "r"(addr));
}
__device__ __forceinline__ void cp16(u32 dst, const void* src) {
    asm volatile("cp.async.cg.shared.global [%0], [%1], 16;" :: "r"(dst), "l"(src));
}

// ---------------- fused prep + fold ----------------
__global__ __launch_bounds__(256) void prep_fold_kernel(
        const float* __restrict__ q, const float* __restrict__ k,
        const float* __restrict__ v,
        const float* __restrict__ Wv, const float* __restrict__ Wo,
        const float* __restrict__ Wq, const float* __restrict__ Aq,
        const float* __restrict__ bqi,
        const float* __restrict__ Wk, const float* __restrict__ Ak,
        const float* __restrict__ bki) {
    __shared__ float pool[8512];
    int bx = blockIdx.x, tid = threadIdx.x;

    if (bx < 768) {
        int t = bx * 256 + tid;
        int sel = t >> 16;
        const float* src = (sel == 0) ? q : (sel == 1) ? k : v;
        __half* dst = (sel == 0) ? g_xq16 : (sel == 1) ? g_xk16 : g_xv16;
        int base = (t & 65535) * 8;
        float4 a = *(const float4*)(src + base);
        float4 b = *(const float4*)(src + base + 4);
        __half2 h0 = __floats2half2_rn(a.x, a.y), h1 = __floats2half2_rn(a.z, a.w);
        __half2 h2 = __floats2half2_rn(b.x, b.y), h3 = __floats2half2_rn(b.z, b.w);
        uint4 u;
        u.x = *(u32*)&h0; u.y = *(u32*)&h1; u.z = *(u32*)&h2; u.w = *(u32*)&h3;
        *(uint4*)(dst + base) = u;
    } else if (bx < 1280) {
        float (*Ts)[33] = (float(*)[33])pool;
        int idx = bx - 768;
        int z = idx >> 8, rem = idx & 255;
        const float* src = z ? Wo : Wv;
        __half* dst = z ? g_Woh : g_Wvh;
        int k0 = (rem >> 4) * 32, n0 = (rem & 15) * 32;
        int r = tid >> 3, c4 = (tid & 7) << 2;
        float4 w = *(const float4*)(src + (size_t)(k0 + r) * Dd + n0 + c4);
        Ts[r][c4 + 0] = w.x; Ts[r][c4 + 1] = w.y;
        Ts[r][c4 + 2] = w.z; Ts[r][c4 + 3] = w.w;
        __syncthreads();
        __half2 h0 = __floats2half2_rn(Ts[c4 + 0][r], Ts[c4 + 1][r]);
        __half2 h1 = __floats2half2_rn(Ts[c4 + 2][r], Ts[c4 + 3][r]);
        uint2 u; u.x = *(u32*)&h0; u.y = *(u32*)&h1;
        *(uint2*)(dst + (size_t)(n0 + r) * Dd + k0 + c4) = u;
    } else {
        float (*At)[68] = (float(*)[68])pool;
        float (*Wt)[65] = (float(*)[65])(pool + 64 * 68);
        int idx = bx - 1280;
        int sel = idx >> 6, h = (idx >> 3) & 7, R0 = (idx & 7) * 64;
        const float* W = sel ? Wk : Wq;
        const float* A = sel ? Ak : Aq;
        const float* bs = sel ? bki : bqi;
        __half* Wd = sel ? g_Wkh : g_Wqh;
        float* bd = sel ? g_bk : g_bq;

        {
            int j = tid >> 2, c0 = (tid & 3) << 4;
            #pragma unroll
            for (int i = 0; i < 4; i++) {
                float4 a = *(const float4*)(A + j * 64 + c0 + i * 4);
                At[j][c0 + i * 4 + 0] = a.x; At[j][c0 + i * 4 + 1] = a.y;
                At[j][c0 + i * 4 + 2] = a.z; At[j][c0 + i * 4 + 3] = a.w;
            }
            int r = tid >> 2, j0 = (tid & 3) << 4;
            #pragma unroll
            for (int i = 0; i < 4; i++) {
                float4 w = *(const float4*)(W + (size_t)(R0 + r) * Dd + h * 64 + j0 + i * 4);
                Wt[j0 + i * 4 + 0][r] = w.x; Wt[j0 + i * 4 + 1][r] = w.y;
                Wt[j0 + i * 4 + 2][r] = w.z; Wt[j0 + i * 4 + 3][r] = w.w;
            }
        }
        __syncthreads();

        int w = tid >> 5, l = tid & 31;
        int c0 = w * 8;
        float acc0[8] = {}, acc1[8] = {};
        #pragma unroll 8
        for (int j = 0; j < 64; j++) {
            float w0 = Wt[j][l], w1 = Wt[j][l + 32];
            float4 a0 = *(const float4*)&At[j][c0];
            float4 a1 = *(const float4*)&At[j][c0 + 4];
            acc0[0] += w0 * a0.x; acc0[1] += w0 * a0.y; acc0[2] += w0 * a0.z; acc0[3] += w0 * a0.w;
            acc0[4] += w0 * a1.x; acc0[5] += w0 * a1.y; acc0[6] += w0 * a1.z; acc0[7] += w0 * a1.w;
            acc1[0] += w1 * a0.x; acc1[1] += w1 * a0.y; acc1[2] += w1 * a0.z; acc1[3] += w1 * a0.w;
            acc1[4] += w1 * a1.x; acc1[5] += w1 * a1.y; acc1[6] += w1 * a1.z; acc1[7] += w1 * a1.w;
        }
        #pragma unroll
        for (int i = 0; i < 8; i++) {
            int c = c0 + i;
            Wd[(size_t)(h * 64 + c) * Dd + R0 + l]      = __float2half(acc0[i]);
            Wd[(size_t)(h * 64 + c) * Dd + R0 + 32 + l] = __float2half(acc1[i]);
        }

        if (R0 == 0 && tid < 64) {
            float bacc = 0.f;
            #pragma unroll 16
            for (int j = 0; j < 64; j++) bacc += bs[h * 64 + j] * At[j][tid];
            bd[h * 64 + tid] = bacc;
        }
    }
}

// ---------------- HMMA tile body: 64m x 64n, K=512, cp.async + ldmatrix ----
template <int MODE>
__device__ __forceinline__ void mma_tile(const __half* __restrict__ X, int lda,
                                         const __half* __restrict__ BT, int ldb,
                                         const float* __restrict__ bias,
                                         __half* __restrict__ outh,
                                         float* __restrict__ outf,
                                         int m0, int n0, int ldo) {
    __shared__ __half As[2][64][40];
    __shared__ __half Bs[2][64][40];
    int tid = threadIdx.x, wid = tid >> 5, lane = tid & 31;
    int wm = (wid & 1) * 32, wn = (wid >> 1) * 16;
    int g = lane >> 2, qd = (lane & 3) * 2;
    int sr = tid >> 2, sk = (tid & 3) * 8;
    int lrow = lane & 15, lcol = (lane >> 4) << 3;

    u32 abase = (u32)__cvta_generic_to_shared(&As[0][0][0]);
    u32 bbase = (u32)__cvta_generic_to_shared(&Bs[0][0][0]);
    const u32 BUFB = 64 * 40 * 2;

    float acc[2][2][4] = {};

    const __half* xg = X + (size_t)(m0 + sr) * lda + sk;
    const __half* bg = BT + (size_t)(n0 + sr) * ldb + sk;
    u32 adst = abase + (sr * 40 + sk) * 2;
    u32 bdst = bbase + (sr * 40 + sk) * 2;

    cp16(adst, xg);
    cp16(bdst, bg);
    asm volatile("cp.async.commit_group;");

    for (int ch = 0; ch < 16; ch++) {
        int buf = ch & 1;
        asm volatile("cp.async.wait_group 0;");
        __syncthreads();
        if (ch < 15) {
            int k0 = (ch + 1) * 32;
            u32 nb = (u32)(buf ^ 1) * BUFB;
            cp16(adst + nb, xg + k0);
            cp16(bdst + nb, bg + k0);
            asm volatile("cp.async.commit_group;");
        }
        u32 abuf = abase + (u32)buf * BUFB;
        u32 bbuf = bbase + (u32)buf * BUFB;
        #pragma unroll
        for (int ks = 0; ks < 32; ks += 16) {
            u32 a[2][4], b[2][2];
            ldsm4(a[0][0], a[0][1], a[0][2], a[0][3],
                  abuf + ((wm + lrow) * 40 + ks + lcol) * 2);
            ldsm4(a[1][0], a[1][1], a[1][2], a[1][3],
                  abuf + ((wm + 16 + lrow) * 40 + ks + lcol) * 2);
            u32 r0, r1, r2, r3;
            ldsm4(r0, r1, r2, r3,
                  bbuf + ((wn + lrow) * 40 + ks + lcol) * 2);
            b[0][0] = r0; b[0][1] = r2; b[1][0] = r1; b[1][1] = r3;
            mma16816(acc[0][0], a[0], b[0]); mma16816(acc[0][1], a[0], b[1]);
            mma16816(acc[1][0], a[1], b[0]); mma16816(acc[1][1], a[1], b[1]);
        }
    }

    #pragma unroll
    for (int mm = 0; mm < 2; mm++) {
        #pragma unroll
        for (int nn = 0; nn < 2; nn++) {
            int M = m0 + wm + mm * 16;
            int N = n0 + wn + nn * 8 + qd;
            float b0 = bias ? bias[N] : 0.f;
            float b1 = bias ? bias[N + 1] : 0.f;
            float c0 = acc[mm][nn][0] + b0, c1 = acc[mm][nn][1] + b1;
            float c2 = acc[mm][nn][2] + b0, c3 = acc[mm][nn][3] + b1;
            if (MODE == 0) {
                __half2 h01 = __floats2half2_rn(c0, c1);
                __half2 h23 = __floats2half2_rn(c2, c3);
                *(u32*)(outh + (size_t)(M + g) * ldo + N)     = *(u32*)&h01;
                *(u32*)(outh + (size_t)(M + g + 8) * ldo + N) = *(u32*)&h23;
            } else if (MODE == 1) {
                int bb = M >> 9;
                int s = (M & 511) + g;
                int h = N >> 6, dd = N & 63;
                __half* r0 = outh + ((size_t)((bb * Hd + h) * HDd + dd)) * Sd;
                __half* r1 = r0 + Sd;
                r0[s] = __float2half(c0); r1[s] = __float2half(c1);
                r0[s + 8] = __float2half(c2); r1[s + 8] = __float2half(c3);
            } else {
                float2 o0 = { c0, c1 }, o1 = { c2, c3 };
                *(float2*)(outf + (size_t)(M + g) * ldo + N)     = o0;
                *(float2*)(outf + (size_t)(M + g + 8) * ldo + N) = o1;
            }
        }
    }
}

__global__ __launch_bounds__(256) void proj_mma_kernel(const float* __restrict__ bv) {
    int z = blockIdx.z;
    int m0 = blockIdx.y * 64, n0 = blockIdx.x * 64;
    if (z == 0)
        mma_tile<0>(g_xq16, Dd, g_Wqh, Dd, g_bq, g_qth, nullptr, m0, n0, Dd);
    else if (z == 1)
        mma_tile<0>(g_xk16, Dd, g_Wkh, Dd, g_bk, g_kth, nullptr, m0, n0, Dd);
    else
        mma_tile<1>(g_xv16, Dd, g_Wvh, Dd, bv, g_v16T, nullptr, m0, n0, 0);
}

__global__ __launch_bounds__(256) void out_mma_kernel(const float* __restrict__ bo,
                                                      float* __restrict__ out) {
    mma_tile<2>(g_ctx16, Dd, g_Woh, Dd, bo, nullptr, out,
                blockIdx.y * 64, blockIdx.x * 64, Dd);
}

// ---------------- scores + softmax + FUSED ctx ----------------
// 512 thr = 16 warps = 16 q rows. Scores: 128-k chunks, XOR-swizzled k tile.
// Then: attn tile -> smem, ctx = attn @ v via HMMA (warps 0-7), direct ctx16 write.
__global__ __launch_bounds__(512, 2) void scores_kernel(const float* __restrict__ av,
                                                        float* __restrict__ attn_out) {
    __shared__ char smpool[34048];
    // phase 1 views
    uint4 (*ks4)[8]  = (uint4(*)[8])smpool;               // [128][8] 16384 B, swizzled
    uint4 (*qs4)[8]  = (uint4(*)[8])(smpool + 16384);     // [16][8]  2048 B
    uint4 *avh4      = (uint4*)(smpool + 18432);          // [8]      128 B
    // phase 2 views (alias: phase-1 data dead by then)
    __half (*att)[520]  = (__half(*)[520])smpool;             // 16640 B
    __half (*vbuf)[136] = (__half(*)[136])(smpool + 16640);  // 17408 B

    int b = blockIdx.z, h = blockIdx.y;
    int q0 = blockIdx.x * 16;
    int tid = threadIdx.x;
    int w = tid >> 5, ln = tid & 31;
    int swl = ln & 7;
    int g = ln >> 2, qd = (ln & 3) * 2;

    if (tid < 128) {
        int row = tid >> 3, c4 = tid & 7;
        qs4[row][c4] =
            *(const uint4*)(g_qth + ((size_t)(b * Sd + q0 + row)) * Dd + h * HDd + c4 * 8);
    } else if (tid < 160) {
        int i = tid - 128;
        __half2 hh = __floats2half2_rn(av[2 * i], av[2 * i + 1]);
        ((u32*)avh4)[i] = *(u32*)&hh;
    }

    float s[4][4];

    for (int ch = 0; ch < 4; ch++) {
        int c0 = ch * 128;
        #pragma unroll
        for (int i = 0; i < 2; i++) {
            int t = tid + i * 512;
            int row = t >> 3, c4 = t & 7;
            ks4[row][c4 ^ (row & 7)] =
                *(const uint4*)(g_kth + ((size_t)(b * Sd + c0 + row)) * Dd + h * HDd + c4 * 8);
        }
        __syncthreads();

        float sa0 = 0.f, sa1 = 0.f, sa2 = 0.f, sa3 = 0.f;
        #pragma unroll
        for (int j = 0; j < 8; j++) {
            uint4 qq = qs4[w][j];
            uint4 aa = avh4[j];
            int sc = j ^ swl;
            uint4 k0 = ks4[ln][sc];
            uint4 k1 = ks4[32 + ln][sc];
            uint4 k2 = ks4[64 + ln][sc];
            uint4 k3 = ks4[96 + ln][sc];
            u32 a0 = 0, a1 = 0, a2 = 0, a3 = 0;
            tchain(qq.x, k0.x, aa.x, a0); tchain(qq.y, k0.y, aa.y, a0);
            tchain(qq.z, k0.z, aa.z, a0); tchain(qq.w, k0.w, aa.w, a0);
            tchain(qq.x, k1.x, aa.x, a1); tchain(qq.y, k1.y, aa.y, a1);
            tchain(qq.z, k1.z, aa.z, a1); tchain(qq.w, k1.w, aa.w, a1);
            tchain(qq.x, k2.x, aa.x, a2); tchain(qq.y, k2.y, aa.y, a2);
            tchain(qq.z, k2.z, aa.z, a2); tchain(qq.w, k2.w, aa.w, a2);
            tchain(qq.x, k3.x, aa.x, a3); tchain(qq.y, k3.y, aa.y, a3);
            tchain(qq.z, k3.z, aa.z, a3); tchain(qq.w, k3.w, aa.w, a3);
            float lo, hi;
            h2f2(a0, lo, hi); sa0 += lo + hi;
            h2f2(a1, lo, hi); sa1 += lo + hi;
            h2f2(a2, lo, hi); sa2 += lo + hi;
            h2f2(a3, lo, hi); sa3 += lo + hi;
        }
        s[ch][0] = sa0; s[ch][1] = sa1; s[ch][2] = sa2; s[ch][3] = sa3;
        __syncthreads();
    }
    // after this barrier nobody reads ks4/qs4/avh4 again

    // softmax (registers + shuffles only)
    float mx = -1e30f;
    #pragma unroll
    for (int ch = 0; ch < 4; ch++)
        #pragma unroll
        for (int m = 0; m < 4; m++) mx = fmaxf(mx, s[ch][m]);
    #pragma unroll
    for (int o = 16; o > 0; o >>= 1) mx = fmaxf(mx, __shfl_xor_sync(0xffffffffu, mx, o));
    float sum = 0.f;
    #pragma unroll
    for (int ch = 0; ch < 4; ch++)
        #pragma unroll
        for (int m = 0; m < 4; m++) { s[ch][m] = __expf(s[ch][m] - mx); sum += s[ch][m]; }
    #pragma unroll
    for (int o = 16; o > 0; o >>= 1) sum += __shfl_xor_sync(0xffffffffu, sum, o);
    float inv = 1.f / sum;

    // write attn: fp32 -> gmem (required output), f16 -> smem tile (for ctx)
    size_t rowoff = (((size_t)(b * Hd + h) * Sd) + q0 + w) * Sd;
    float* arow = attn_out + rowoff;
    #pragma unroll
    for (int ch = 0; ch < 4; ch++)
        #pragma unroll
        for (int m = 0; m < 4; m++) {
            float a = s[ch][m] * inv;
            int kk = ch * 128 + m * 32 + ln;
            arow[kk] = a;
            att[w][kk] = __float2half(a);
        }

    // -------- fused ctx: ctx[16 q][64 d] = att[16][512] @ v[512][64] --------
    const __half* vsrc = g_v16T + ((size_t)((b * Hd + h) * HDd)) * Sd;
    u32 vbase = (u32)__cvta_generic_to_shared(&vbuf[0][0]);
    int wn = (w & 7) * 8;
    float cacc[4] = {0.f, 0.f, 0.f, 0.f};

    for (int kc = 0; kc < 4; kc++) {
        __syncthreads();   // att visible (kc=0) / previous vbuf reads done
        #pragma unroll
        for (int i = 0; i < 2; i++) {
            int t = tid + i * 512;
            int dRow = t >> 4, cs = (t & 15) * 8;
            cp16(vbase + (dRow * 136 + cs) * 2,
                 vsrc + (size_t)dRow * Sd + kc * 128 + cs);
        }
        asm volatile("cp.async.commit_group;");
        asm volatile("cp.async.wait_group 0;");
        __syncthreads();
        if (w < 8) {
            #pragma unroll
            for (int ks = 0; ks < 8; ks++) {
                int kcol = kc * 128 + ks * 16;
                u32 a[4], bf[2];
                a[0] = *(const u32*)&att[g][kcol + qd];
                a[1] = *(const u32*)&att[g + 8][kcol + qd];
                a[2] = *(const u32*)&att[g][kcol + qd + 8];
                a[3] = *(const u32*)&att[g + 8][kcol + qd + 8];
                bf[0] = *(const u32*)&vbuf[wn + g][ks * 16 + qd];
                bf[1] = *(const u32*)&vbuf[wn + g][ks * 16 + qd + 8];
                mma16816(cacc, a, bf);
            }
        }
    }

    if (w < 8) {
        int dcol = h * 64 + wn + qd;
        __half2 h01 = __floats2half2_rn(cacc[0], cacc[1]);
        __half2 h23 = __floats2half2_rn(cacc[2], cacc[3]);
        *(u32*)(g_ctx16 + (size_t)(b * Sd + q0 + g) * Dd + dcol)     = *(u32*)&h01;
        *(u32*)(g_ctx16 + (size_t)(b * Sd + q0 + g + 8) * Dd + dcol) = *(u32*)&h23;
    }
}

// ---------------- launch ----------------
extern "C" void kernel_launch(void* const* d_in, const int* in_sizes, int n_in,
                              void* d_out, int out_size) {
    const float* query = (const float*)d_in[0];
    const float* key_  = (const float*)d_in[1];
    const float* value = (const float*)d_in[2];
    const float* Wq    = (const float*)d_in[3];
    const float* bq    = (const float*)d_in[4];
    const float* Wk    = (const float*)d_in[5];
    const float* bk    = (const float*)d_in[6];
    const float* Wv    = (const float*)d_in[7];
    const float* bv    = (const float*)d_in[8];
    const float* Wo    = (const float*)d_in[9];
    const float* bo    = (const float*)d_in[10];
    const float* Aq    = (const float*)d_in[11];
    const float* Ak    = (const float*)d_in[12];
    const float* av    = (const float*)d_in[13];

    float* out      = (float*)d_out;                  // [B,S,D]
    float* attn_out = out + (size_t)Bd * Sd * Dd;     // [B,H,S,S]

    prep_fold_kernel<<<1408, 256>>>(query, key_, value, Wv, Wo,
                                    Wq, Aq, bq, Wk, Ak, bk);
    proj_mma_kernel<<<dim3(8, 16, 3), 256>>>(bv);
    scores_kernel<<<dim3(32, Hd, Bd), 512>>>(av, attn_out);
    out_mma_kernel<<<dim3(8, 16), 256>>>(bo, out);
}

// round 10
// speedup vs baseline: 2.7383x; 1.0289x over previous
#include <cuda_runtime.h>
#include <cuda_fp16.h>

#define Dd  512
#define Sd  512
#define Bd  2
#define Hd  8
#define HDd 64

typedef unsigned long long u64;
typedef unsigned int u32;

// ---------------- scratch (device globals) ----------------
__device__ __half g_Wqh[Dd * Dd];       // folded Wq@Aq, transposed [n][k], f16
__device__ __half g_Wkh[Dd * Dd];       // folded Wk@Ak, transposed [n][k], f16
__device__ __half g_Wvh[Dd * Dd];       // Wv transposed [n][k], f16
__device__ __half g_Woh[Dd * Dd];       // Wo transposed [n][k], f16
__device__ float  g_bq[Dd];
__device__ float  g_bk[Dd];
__device__ __half g_xq16[Bd * Sd * Dd];
__device__ __half g_xk16[Bd * Sd * Dd];
__device__ __half g_xv16[Bd * Sd * Dd];
__device__ __half g_qth[Bd * Sd * Dd];  // q_term f16, row-major
__device__ __half g_kth[Bd * Sd * Dd];  // k_term f16
__device__ __half g_v16T[Bd * Hd * HDd * Sd]; // v, per (b,h) transposed [d][s]
__device__ __half g_ctx16[Bd * Sd * Dd];      // ctx f16, row-major

// ---------------- asm helpers ----------------
__device__ __forceinline__ void h2f2(u32 h, float& lo, float& hi) {
    asm("{ .reg .b16 l, h;\n\t mov.b32 {l, h}, %2;\n\t"
        " cvt.f32.f16 %0, l;\n\t cvt.f32.f16 %1, h; }"
        : "=f"(lo), "=f"(hi) : "r"(h));
}
__device__ __forceinline__ void tchain(u32 q2, u32 k2, u32 a2, u32& acch) {
    u32 x2, t2;
    asm("add.rn.f16x2 %0, %1, %2;" : "=r"(x2) : "r"(q2), "r"(k2));
    asm("tanh.approx.f16x2 %0, %1;" : "=r"(t2) : "r"(x2));
    asm("fma.rn.f16x2 %0, %1, %2, %0;" : "+r"(acch) : "r"(t2), "r"(a2));
}
__device__ __forceinline__ void mma16816(float* d, const u32* a, const u32* b) {
    asm volatile(
        "mma.sync.aligned.m16n8k16.row.col.f32.f16.f16.f32 "
        "{%0,%1,%2,%3}, {%4,%5,%6,%7}, {%8,%9}, {%0,%1,%2,%3};"
        : "+f"(d[0]), "+f"(d[1]), "+f"(d[2]), "+f"(d[3])
        : "r"(a[0]), "r"(a[1]), "r"(a[2]), "r"(a[3]), "r"(b[0]), "r"(b[1]));
}
__device__ __forceinline__ void ldsm4(u32& r0, u32& r1, u32& r2, u32& r3, u32 addr) {
    asm volatile("ldmatrix.sync.aligned.m8n8.x4.shared.b16 {%0,%1,%2,%3}, [%4];"
                 : "=r"(r0), "=r"(r1), "=r"(r2), "=r"(r3) : "r"(addr));
}
__device__ __forceinline__ void cp16(u32 dst, const void* src) {
    asm volatile("cp.async.cg.shared.global [%0], [%1], 16;" :: "r"(dst), "l"(src));
}

// ---------------- fused prep + fold ----------------
__global__ __launch_bounds__(256) void prep_fold_kernel(
        const float* __restrict__ q, const float* __restrict__ k,
        const float* __restrict__ v,
        const float* __restrict__ Wv, const float* __restrict__ Wo,
        const float* __restrict__ Wq, const float* __restrict__ Aq,
        const float* __restrict__ bqi,
        const float* __restrict__ Wk, const float* __restrict__ Ak,
        const float* __restrict__ bki) {
    __shared__ float pool[8512];
    int bx = blockIdx.x, tid = threadIdx.x;

    if (bx < 768) {
        int t = bx * 256 + tid;
        int sel = t >> 16;
        const float* src = (sel == 0) ? q : (sel == 1) ? k : v;
        __half* dst = (sel == 0) ? g_xq16 : (sel == 1) ? g_xk16 : g_xv16;
        int base = (t & 65535) * 8;
        float4 a = *(const float4*)(src + base);
        float4 b = *(const float4*)(src + base + 4);
        __half2 h0 = __floats2half2_rn(a.x, a.y), h1 = __floats2half2_rn(a.z, a.w);
        __half2 h2 = __floats2half2_rn(b.x, b.y), h3 = __floats2half2_rn(b.z, b.w);
        uint4 u;
        u.x = *(u32*)&h0; u.y = *(u32*)&h1; u.z = *(u32*)&h2; u.w = *(u32*)&h3;
        *(uint4*)(dst + base) = u;
    } else if (bx < 1280) {
        float (*Ts)[33] = (float(*)[33])pool;
        int idx = bx - 768;
        int z = idx >> 8, rem = idx & 255;
        const float* src = z ? Wo : Wv;
        __half* dst = z ? g_Woh : g_Wvh;
        int k0 = (rem >> 4) * 32, n0 = (rem & 15) * 32;
        int r = tid >> 3, c4 = (tid & 7) << 2;
        float4 w = *(const float4*)(src + (size_t)(k0 + r) * Dd + n0 + c4);
        Ts[r][c4 + 0] = w.x; Ts[r][c4 + 1] = w.y;
        Ts[r][c4 + 2] = w.z; Ts[r][c4 + 3] = w.w;
        __syncthreads();
        __half2 h0 = __floats2half2_rn(Ts[c4 + 0][r], Ts[c4 + 1][r]);
        __half2 h1 = __floats2half2_rn(Ts[c4 + 2][r], Ts[c4 + 3][r]);
        uint2 u; u.x = *(u32*)&h0; u.y = *(u32*)&h1;
        *(uint2*)(dst + (size_t)(n0 + r) * Dd + k0 + c4) = u;
    } else {
        float (*At)[68] = (float(*)[68])pool;
        float (*Wt)[65] = (float(*)[65])(pool + 64 * 68);
        int idx = bx - 1280;
        int sel = idx >> 6, h = (idx >> 3) & 7, R0 = (idx & 7) * 64;
        const float* W = sel ? Wk : Wq;
        const float* A = sel ? Ak : Aq;
        const float* bs = sel ? bki : bqi;
        __half* Wd = sel ? g_Wkh : g_Wqh;
        float* bd = sel ? g_bk : g_bq;

        {
            int j = tid >> 2, c0 = (tid & 3) << 4;
            #pragma unroll
            for (int i = 0; i < 4; i++) {
                float4 a = *(const float4*)(A + j * 64 + c0 + i * 4);
                At[j][c0 + i * 4 + 0] = a.x; At[j][c0 + i * 4 + 1] = a.y;
                At[j][c0 + i * 4 + 2] = a.z; At[j][c0 + i * 4 + 3] = a.w;
            }
            int r = tid >> 2, j0 = (tid & 3) << 4;
            #pragma unroll
            for (int i = 0; i < 4; i++) {
                float4 w = *(const float4*)(W + (size_t)(R0 + r) * Dd + h * 64 + j0 + i * 4);
                Wt[j0 + i * 4 + 0][r] = w.x; Wt[j0 + i * 4 + 1][r] = w.y;
                Wt[j0 + i * 4 + 2][r] = w.z; Wt[j0 + i * 4 + 3][r] = w.w;
            }
        }
        __syncthreads();

        int w = tid >> 5, l = tid & 31;
        int c0 = w * 8;
        float acc0[8] = {}, acc1[8] = {};
        #pragma unroll 8
        for (int j = 0; j < 64; j++) {
            float w0 = Wt[j][l], w1 = Wt[j][l + 32];
            float4 a0 = *(const float4*)&At[j][c0];
            float4 a1 = *(const float4*)&At[j][c0 + 4];
            acc0[0] += w0 * a0.x; acc0[1] += w0 * a0.y; acc0[2] += w0 * a0.z; acc0[3] += w0 * a0.w;
            acc0[4] += w0 * a1.x; acc0[5] += w0 * a1.y; acc0[6] += w0 * a1.z; acc0[7] += w0 * a1.w;
            acc1[0] += w1 * a0.x; acc1[1] += w1 * a0.y; acc1[2] += w1 * a0.z; acc1[3] += w1 * a0.w;
            acc1[4] += w1 * a1.x; acc1[5] += w1 * a1.y; acc1[6] += w1 * a1.z; acc1[7] += w1 * a1.w;
        }
        #pragma unroll
        for (int i = 0; i < 8; i++) {
            int c = c0 + i;
            Wd[(size_t)(h * 64 + c) * Dd + R0 + l]      = __float2half(acc0[i]);
            Wd[(size_t)(h * 64 + c) * Dd + R0 + 32 + l] = __float2half(acc1[i]);
        }

        if (R0 == 0 && tid < 64) {
            float bacc = 0.f;
            #pragma unroll 16
            for (int j = 0; j < 64; j++) bacc += bs[h * 64 + j] * At[j][tid];
            bd[h * 64 + tid] = bacc;
        }
    }
}

// ---------------- HMMA tile body: 64m x 64n, K=512, 3-stage cp.async ----------
template <int MODE>
__device__ __forceinline__ void mma_tile(const __half* __restrict__ X, int lda,
                                         const __half* __restrict__ BT, int ldb,
                                         const float* __restrict__ bias,
                                         __half* __restrict__ outh,
                                         float* __restrict__ outf,
                                         int m0, int n0, int ldo) {
    __shared__ __half As[3][64][40];
    __shared__ __half Bs[3][64][40];
    int tid = threadIdx.x, wid = tid >> 5, lane = tid & 31;
    int wm = (wid & 1) * 32, wn = (wid >> 1) * 16;
    int g = lane >> 2, qd = (lane & 3) * 2;
    int sr = tid >> 2, sk = (tid & 3) * 8;
    int lrow = lane & 15, lcol = (lane >> 4) << 3;

    u32 abase = (u32)__cvta_generic_to_shared(&As[0][0][0]);
    u32 bbase = (u32)__cvta_generic_to_shared(&Bs[0][0][0]);
    const u32 BUFB = 64 * 40 * 2;

    float acc[2][2][4] = {};

    const __half* xg = X + (size_t)(m0 + sr) * lda + sk;
    const __half* bg = BT + (size_t)(n0 + sr) * ldb + sk;
    u32 adst = abase + (sr * 40 + sk) * 2;
    u32 bdst = bbase + (sr * 40 + sk) * 2;

    // prologue: chunks 0 and 1 in flight
    cp16(adst, xg);
    cp16(bdst, bg);
    asm volatile("cp.async.commit_group;");
    cp16(adst + BUFB, xg + 32);
    cp16(bdst + BUFB, bg + 32);
    asm volatile("cp.async.commit_group;");

    int buf = 0;
    for (int ch = 0; ch < 16; ch++) {
        if (ch < 15) asm volatile("cp.async.wait_group 1;");
        else         asm volatile("cp.async.wait_group 0;");
        __syncthreads();
        if (ch + 2 < 16) {
            int k0 = (ch + 2) * 32;
            int nb = buf + 2; if (nb >= 3) nb -= 3;   // (ch+2) % 3
            cp16(adst + (u32)nb * BUFB, xg + k0);
            cp16(bdst + (u32)nb * BUFB, bg + k0);
            asm volatile("cp.async.commit_group;");
        }
        u32 abuf = abase + (u32)buf * BUFB;
        u32 bbuf = bbase + (u32)buf * BUFB;
        #pragma unroll
        for (int ks = 0; ks < 32; ks += 16) {
            u32 a[2][4], b[2][2];
            ldsm4(a[0][0], a[0][1], a[0][2], a[0][3],
                  abuf + ((wm + lrow) * 40 + ks + lcol) * 2);
            ldsm4(a[1][0], a[1][1], a[1][2], a[1][3],
                  abuf + ((wm + 16 + lrow) * 40 + ks + lcol) * 2);
            u32 r0, r1, r2, r3;
            ldsm4(r0, r1, r2, r3,
                  bbuf + ((wn + lrow) * 40 + ks + lcol) * 2);
            b[0][0] = r0; b[0][1] = r2; b[1][0] = r1; b[1][1] = r3;
            mma16816(acc[0][0], a[0], b[0]); mma16816(acc[0][1], a[0], b[1]);
            mma16816(acc[1][0], a[1], b[0]); mma16816(acc[1][1], a[1], b[1]);
        }
        if (++buf == 3) buf = 0;
    }

    #pragma unroll
    for (int mm = 0; mm < 2; mm++) {
        #pragma unroll
        for (int nn = 0; nn < 2; nn++) {
            int M = m0 + wm + mm * 16;
            int N = n0 + wn + nn * 8 + qd;
            float b0 = bias ? bias[N] : 0.f;
            float b1 = bias ? bias[N + 1] : 0.f;
            float c0 = acc[mm][nn][0] + b0, c1 = acc[mm][nn][1] + b1;
            float c2 = acc[mm][nn][2] + b0, c3 = acc[mm][nn][3] + b1;
            if (MODE == 0) {
                __half2 h01 = __floats2half2_rn(c0, c1);
                __half2 h23 = __floats2half2_rn(c2, c3);
                *(u32*)(outh + (size_t)(M + g) * ldo + N)     = *(u32*)&h01;
                *(u32*)(outh + (size_t)(M + g + 8) * ldo + N) = *(u32*)&h23;
            } else if (MODE == 1) {
                int bb = M >> 9;
                int s = (M & 511) + g;
                int h = N >> 6, dd = N & 63;
                __half* r0 = outh + ((size_t)((bb * Hd + h) * HDd + dd)) * Sd;
                __half* r1 = r0 + Sd;
                r0[s] = __float2half(c0); r1[s] = __float2half(c1);
                r0[s + 8] = __float2half(c2); r1[s + 8] = __float2half(c3);
            } else {
                float2 o0 = { c0, c1 }, o1 = { c2, c3 };
                *(float2*)(outf + (size_t)(M + g) * ldo + N)     = o0;
                *(float2*)(outf + (size_t)(M + g + 8) * ldo + N) = o1;
            }
        }
    }
}

__global__ __launch_bounds__(256) void proj_mma_kernel(const float* __restrict__ bv) {
    int z = blockIdx.z;
    int m0 = blockIdx.y * 64, n0 = blockIdx.x * 64;
    if (z == 0)
        mma_tile<0>(g_xq16, Dd, g_Wqh, Dd, g_bq, g_qth, nullptr, m0, n0, Dd);
    else if (z == 1)
        mma_tile<0>(g_xk16, Dd, g_Wkh, Dd, g_bk, g_kth, nullptr, m0, n0, Dd);
    else
        mma_tile<1>(g_xv16, Dd, g_Wvh, Dd, bv, g_v16T, nullptr, m0, n0, 0);
}

__global__ __launch_bounds__(256) void out_mma_kernel(const float* __restrict__ bo,
                                                      float* __restrict__ out) {
    mma_tile<2>(g_ctx16, Dd, g_Woh, Dd, bo, nullptr, out,
                blockIdx.y * 64, blockIdx.x * 64, Dd);
}

// ---------------- scores + softmax + fused ctx ----------------
// 512 thr = 16 warps = 16 q rows. k staged via double-buffered cp.async
// (copy of chunk ch+1 overlaps tanh burst of chunk ch).
__global__ __launch_bounds__(512, 2) void scores_kernel(const float* __restrict__ av,
                                                        float* __restrict__ attn_out) {
    __shared__ char smpool[34944];
    // phase 1: ks buf0 @0 (16384), ks buf1 @16384 (16384), qs @32768 (2048), avh @34816 (128)
    uint4 (*qs4)[8] = (uint4(*)[8])(smpool + 32768);
    uint4 *avh4     = (uint4*)(smpool + 34816);
    // phase 2 (alias; protected by barrier after score loop)
    __half (*att)[520]  = (__half(*)[520])smpool;             // 16640 B
    __half (*vbuf)[136] = (__half(*)[136])(smpool + 16640);   // 17408 B

    int b = blockIdx.z, h = blockIdx.y;
    int q0 = blockIdx.x * 16;
    int tid = threadIdx.x;
    int w = tid >> 5, ln = tid & 31;
    int swl = ln & 7;
    int g = ln >> 2, qd = (ln & 3) * 2;

    u32 ksbase = (u32)__cvta_generic_to_shared(smpool);
    const __half* ksrc = g_kth + ((size_t)(b * Sd)) * Dd + h * HDd;

    // stage chunk 0 (async, swizzled)
    {
        #pragma unroll
        for (int i = 0; i < 2; i++) {
            int t = tid + i * 512;
            int row = t >> 3, c4 = t & 7;
            cp16(ksbase + (((row << 3) + (c4 ^ (row & 7))) << 4),
                 ksrc + (size_t)row * Dd + c4 * 8);
        }
        asm volatile("cp.async.commit_group;");
    }
    if (tid < 128) {
        int row = tid >> 3, c4 = tid & 7;
        qs4[row][c4] =
            *(const uint4*)(g_qth + ((size_t)(b * Sd + q0 + row)) * Dd + h * HDd + c4 * 8);
    } else if (tid < 160) {
        int i = tid - 128;
        __half2 hh = __floats2half2_rn(av[2 * i], av[2 * i + 1]);
        ((u32*)avh4)[i] = *(u32*)&hh;
    }

    float s[4][4];

    for (int ch = 0; ch < 4; ch++) {
        asm volatile("cp.async.wait_group 0;");
        __syncthreads();
        if (ch < 3) {   // stage chunk ch+1 into other buffer; overlaps compute below
            u32 kb = ksbase + (u32)((ch + 1) & 1) * 16384;
            const __half* src = ksrc + (size_t)(ch + 1) * 128 * Dd;
            #pragma unroll
            for (int i = 0; i < 2; i++) {
                int t = tid + i * 512;
                int row = t >> 3, c4 = t & 7;
                cp16(kb + (((row << 3) + (c4 ^ (row & 7))) << 4),
                     src + (size_t)row * Dd + c4 * 8);
            }
            asm volatile("cp.async.commit_group;");
        }

        uint4 (*ks4)[8] = (uint4(*)[8])(smpool + (u32)(ch & 1) * 16384);
        float sa0 = 0.f, sa1 = 0.f, sa2 = 0.f, sa3 = 0.f;
        #pragma unroll
        for (int j = 0; j < 8; j++) {
            uint4 qq = qs4[w][j];
            uint4 aa = avh4[j];
            int sc = j ^ swl;
            uint4 k0 = ks4[ln][sc];
            uint4 k1 = ks4[32 + ln][sc];
            uint4 k2 = ks4[64 + ln][sc];
            uint4 k3 = ks4[96 + ln][sc];
            u32 a0 = 0, a1 = 0, a2 = 0, a3 = 0;
            tchain(qq.x, k0.x, aa.x, a0); tchain(qq.y, k0.y, aa.y, a0);
            tchain(qq.z, k0.z, aa.z, a0); tchain(qq.w, k0.w, aa.w, a0);
            tchain(qq.x, k1.x, aa.x, a1); tchain(qq.y, k1.y, aa.y, a1);
            tchain(qq.z, k1.z, aa.z, a1); tchain(qq.w, k1.w, aa.w, a1);
            tchain(qq.x, k2.x, aa.x, a2); tchain(qq.y, k2.y, aa.y, a2);
            tchain(qq.z, k2.z, aa.z, a2); tchain(qq.w, k2.w, aa.w, a2);
            tchain(qq.x, k3.x, aa.x, a3); tchain(qq.y, k3.y, aa.y, a3);
            tchain(qq.z, k3.z, aa.z, a3); tchain(qq.w, k3.w, aa.w, a3);
            float lo, hi;
            h2f2(a0, lo, hi); sa0 += lo + hi;
            h2f2(a1, lo, hi); sa1 += lo + hi;
            h2f2(a2, lo, hi); sa2 += lo + hi;
            h2f2(a3, lo, hi); sa3 += lo + hi;
        }
        s[ch][0] = sa0; s[ch][1] = sa1; s[ch][2] = sa2; s[ch][3] = sa3;
    }
    __syncthreads();   // all chunk computes done before att aliases ks buffers

    // softmax (registers + shuffles only)
    float mx = -1e30f;
    #pragma unroll
    for (int ch = 0; ch < 4; ch++)
        #pragma unroll
        for (int m = 0; m < 4; m++) mx = fmaxf(mx, s[ch][m]);
    #pragma unroll
    for (int o = 16; o > 0; o >>= 1) mx = fmaxf(mx, __shfl_xor_sync(0xffffffffu, mx, o));
    float sum = 0.f;
    #pragma unroll
    for (int ch = 0; ch < 4; ch++)
        #pragma unroll
        for (int m = 0; m < 4; m++) { s[ch][m] = __expf(s[ch][m] - mx); sum += s[ch][m]; }
    #pragma unroll
    for (int o = 16; o > 0; o >>= 1) sum += __shfl_xor_sync(0xffffffffu, sum, o);
    float inv = 1.f / sum;

    // write attn: fp32 -> gmem (required output), f16 -> smem tile (for ctx)
    size_t rowoff = (((size_t)(b * Hd + h) * Sd) + q0 + w) * Sd;
    float* arow = attn_out + rowoff;
    #pragma unroll
    for (int ch = 0; ch < 4; ch++)
        #pragma unroll
        for (int m = 0; m < 4; m++) {
            float a = s[ch][m] * inv;
            int kk = ch * 128 + m * 32 + ln;
            arow[kk] = a;
            att[w][kk] = __float2half(a);
        }

    // -------- fused ctx: ctx[16 q][64 d] = att[16][512] @ v[512][64] --------
    const __half* vsrc = g_v16T + ((size_t)((b * Hd + h) * HDd)) * Sd;
    u32 vbase = (u32)__cvta_generic_to_shared(&vbuf[0][0]);
    int wn = (w & 7) * 8;
    float cacc[4] = {0.f, 0.f, 0.f, 0.f};

    for (int kc = 0; kc < 4; kc++) {
        __syncthreads();
        #pragma unroll
        for (int i = 0; i < 2; i++) {
            int t = tid + i * 512;
            int dRow = t >> 4, cs = (t & 15) * 8;
            cp16(vbase + (dRow * 136 + cs) * 2,
                 vsrc + (size_t)dRow * Sd + kc * 128 + cs);
        }
        asm volatile("cp.async.commit_group;");
        asm volatile("cp.async.wait_group 0;");
        __syncthreads();
        if (w < 8) {
            #pragma unroll
            for (int ks = 0; ks < 8; ks++) {
                int kcol = kc * 128 + ks * 16;
                u32 a[4], bf[2];
                a[0] = *(const u32*)&att[g][kcol + qd];
                a[1] = *(const u32*)&att[g + 8][kcol + qd];
                a[2] = *(const u32*)&att[g][kcol + qd + 8];
                a[3] = *(const u32*)&att[g + 8][kcol + qd + 8];
                bf[0] = *(const u32*)&vbuf[wn + g][ks * 16 + qd];
                bf[1] = *(const u32*)&vbuf[wn + g][ks * 16 + qd + 8];
                mma16816(cacc, a, bf);
            }
        }
    }

    if (w < 8) {
        int dcol = h * 64 + wn + qd;
        __half2 h01 = __floats2half2_rn(cacc[0], cacc[1]);
        __half2 h23 = __floats2half2_rn(cacc[2], cacc[3]);
        *(u32*)(g_ctx16 + (size_t)(b * Sd + q0 + g) * Dd + dcol)     = *(u32*)&h01;
        *(u32*)(g_ctx16 + (size_t)(b * Sd + q0 + g + 8) * Dd + dcol) = *(u32*)&h23;
    }
}

// ---------------- launch ----------------
extern "C" void kernel_launch(void* const* d_in, const int* in_sizes, int n_in,
                              void* d_out, int out_size) {
    const float* query = (const float*)d_in[0];
    const float* key_  = (const float*)d_in[1];
    const float* value = (const float*)d_in[2];
    const float* Wq    = (const float*)d_in[3];
    const float* bq    = (const float*)d_in[4];
    const float* Wk    = (const float*)d_in[5];
    const float* bk    = (const float*)d_in[6];
    const float* Wv    = (const float*)d_in[7];
    const float* bv    = (const float*)d_in[8];
    const float* Wo    = (const float*)d_in[9];
    const float* bo    = (const float*)d_in[10];
    const float* Aq    = (const float*)d_in[11];
    const float* Ak    = (const float*)d_in[12];
    const float* av    = (const float*)d_in[13];

    float* out      = (float*)d_out;                  // [B,S,D]
    float* attn_out = out + (size_t)Bd * Sd * Dd;     // [B,H,S,S]

    prep_fold_kernel<<<1408, 256>>>(query, key_, value, Wv, Wo,
                                    Wq, Aq, bq, Wk, Ak, bk);
    proj_mma_kernel<<<dim3(8, 16, 3), 256>>>(bv);
    scores_kernel<<<dim3(32, Hd, Bd), 512>>>(av, attn_out);
    out_mma_kernel<<<dim3(8, 16), 256>>>(bo, out);
}

// round 11
// speedup vs baseline: 2.8666x; 1.0469x over previous
#include <cuda_runtime.h>
#include <cuda_fp16.h>

#define Dd  512
#define Sd  512
#define Bd  2
#define Hd  8
#define HDd 64

typedef unsigned long long u64;
typedef unsigned int u32;

// ---------------- scratch (device globals) ----------------
__device__ __half g_Wqh[Dd * Dd];       // folded Wq@Aq, transposed [n][k], f16
__device__ __half g_Wkh[Dd * Dd];       // folded Wk@Ak, transposed [n][k], f16
__device__ __half g_Wvh[Dd * Dd];       // Wv transposed [n][k], f16
__device__ __half g_Woh[Dd * Dd];       // Wo transposed [n][k], f16
__device__ float  g_bq[Dd];
__device__ float  g_bk[Dd];
__device__ __half g_xq16[Bd * Sd * Dd];
__device__ __half g_xk16[Bd * Sd * Dd];
__device__ __half g_xv16[Bd * Sd * Dd];
__device__ __half g_qth[Bd * Sd * Dd];  // q_term f16, row-major
__device__ __half g_kth[Bd * Sd * Dd];  // k_term f16
__device__ __half g_v16T[Bd * Hd * HDd * Sd]; // v, per (b,h) transposed [d][s]
__device__ __half g_ctx16[Bd * Sd * Dd];      // ctx f16, row-major

// ---------------- asm helpers ----------------
__device__ __forceinline__ void h2f2(u32 h, float& lo, float& hi) {
    asm("{ .reg .b16 l, h;\n\t mov.b32 {l, h}, %2;\n\t"
        " cvt.f32.f16 %0, l;\n\t cvt.f32.f16 %1, h; }"
        : "=f"(lo), "=f"(hi) : "r"(h));
}
__device__ __forceinline__ void tchain(u32 q2, u32 k2, u32 a2, u32& acch) {
    u32 x2, t2;
    asm("add.rn.f16x2 %0, %1, %2;" : "=r"(x2) : "r"(q2), "r"(k2));
    asm("tanh.approx.f16x2 %0, %1;" : "=r"(t2) : "r"(x2));
    asm("fma.rn.f16x2 %0, %1, %2, %0;" : "+r"(acch) : "r"(t2), "r"(a2));
}
__device__ __forceinline__ void mma16816(float* d, const u32* a, const u32* b) {
    asm volatile(
        "mma.sync.aligned.m16n8k16.row.col.f32.f16.f16.f32 "
        "{%0,%1,%2,%3}, {%4,%5,%6,%7}, {%8,%9}, {%0,%1,%2,%3};"
        : "+f"(d[0]), "+f"(d[1]), "+f"(d[2]), "+f"(d[3])
        : "r"(a[0]), "r"(a[1]), "r"(a[2]), "r"(a[3]), "r"(b[0]), "r"(b[1]));
}
__device__ __forceinline__ void ldsm4(u32& r0, u32& r1, u32& r2, u32& r3, u32 addr) {
    asm volatile("ldmatrix.sync.aligned.m8n8.x4.shared.b16 {%0,%1,%2,%3}, [%4];"
                 : "=r"(r0), "=r"(r1), "=r"(r2), "=r"(r3) : "r"(addr));
}
__device__ __forceinline__ void cp16(u32 dst, const void* src) {
    asm volatile("cp.async.cg.shared.global [%0], [%1], 16;" :: "r"(dst), "l"(src));
}

// ---------------- fused prep + fold (unchanged) ----------------
__global__ __launch_bounds__(256) void prep_fold_kernel(
        const float* __restrict__ q, const float* __restrict__ k,
        const float* __restrict__ v,
        const float* __restrict__ Wv, const float* __restrict__ Wo,
        const float* __restrict__ Wq, const float* __restrict__ Aq,
        const float* __restrict__ bqi,
        const float* __restrict__ Wk, const float* __restrict__ Ak,
        const float* __restrict__ bki) {
    __shared__ float pool[8512];
    int bx = blockIdx.x, tid = threadIdx.x;

    if (bx < 768) {
        int t = bx * 256 + tid;
        int sel = t >> 16;
        const float* src = (sel == 0) ? q : (sel == 1) ? k : v;
        __half* dst = (sel == 0) ? g_xq16 : (sel == 1) ? g_xk16 : g_xv16;
        int base = (t & 65535) * 8;
        float4 a = *(const float4*)(src + base);
        float4 b = *(const float4*)(src + base + 4);
        __half2 h0 = __floats2half2_rn(a.x, a.y), h1 = __floats2half2_rn(a.z, a.w);
        __half2 h2 = __floats2half2_rn(b.x, b.y), h3 = __floats2half2_rn(b.z, b.w);
        uint4 u;
        u.x = *(u32*)&h0; u.y = *(u32*)&h1; u.z = *(u32*)&h2; u.w = *(u32*)&h3;
        *(uint4*)(dst + base) = u;
    } else if (bx < 1280) {
        float (*Ts)[33] = (float(*)[33])pool;
        int idx = bx - 768;
        int z = idx >> 8, rem = idx & 255;
        const float* src = z ? Wo : Wv;
        __half* dst = z ? g_Woh : g_Wvh;
        int k0 = (rem >> 4) * 32, n0 = (rem & 15) * 32;
        int r = tid >> 3, c4 = (tid & 7) << 2;
        float4 w = *(const float4*)(src + (size_t)(k0 + r) * Dd + n0 + c4);
        Ts[r][c4 + 0] = w.x; Ts[r][c4 + 1] = w.y;
        Ts[r][c4 + 2] = w.z; Ts[r][c4 + 3] = w.w;
        __syncthreads();
        __half2 h0 = __floats2half2_rn(Ts[c4 + 0][r], Ts[c4 + 1][r]);
        __half2 h1 = __floats2half2_rn(Ts[c4 + 2][r], Ts[c4 + 3][r]);
        uint2 u; u.x = *(u32*)&h0; u.y = *(u32*)&h1;
        *(uint2*)(dst + (size_t)(n0 + r) * Dd + k0 + c4) = u;
    } else {
        float (*At)[68] = (float(*)[68])pool;
        float (*Wt)[65] = (float(*)[65])(pool + 64 * 68);
        int idx = bx - 1280;
        int sel = idx >> 6, h = (idx >> 3) & 7, R0 = (idx & 7) * 64;
        const float* W = sel ? Wk : Wq;
        const float* A = sel ? Ak : Aq;
        const float* bs = sel ? bki : bqi;
        __half* Wd = sel ? g_Wkh : g_Wqh;
        float* bd = sel ? g_bk : g_bq;

        {
            int j = tid >> 2, c0 = (tid & 3) << 4;
            #pragma unroll
            for (int i = 0; i < 4; i++) {
                float4 a = *(const float4*)(A + j * 64 + c0 + i * 4);
                At[j][c0 + i * 4 + 0] = a.x; At[j][c0 + i * 4 + 1] = a.y;
                At[j][c0 + i * 4 + 2] = a.z; At[j][c0 + i * 4 + 3] = a.w;
            }
            int r = tid >> 2, j0 = (tid & 3) << 4;
            #pragma unroll
            for (int i = 0; i < 4; i++) {
                float4 w = *(const float4*)(W + (size_t)(R0 + r) * Dd + h * 64 + j0 + i * 4);
                Wt[j0 + i * 4 + 0][r] = w.x; Wt[j0 + i * 4 + 1][r] = w.y;
                Wt[j0 + i * 4 + 2][r] = w.z; Wt[j0 + i * 4 + 3][r] = w.w;
            }
        }
        __syncthreads();

        int w = tid >> 5, l = tid & 31;
        int c0 = w * 8;
        float acc0[8] = {}, acc1[8] = {};
        #pragma unroll 8
        for (int j = 0; j < 64; j++) {
            float w0 = Wt[j][l], w1 = Wt[j][l + 32];
            float4 a0 = *(const float4*)&At[j][c0];
            float4 a1 = *(const float4*)&At[j][c0 + 4];
            acc0[0] += w0 * a0.x; acc0[1] += w0 * a0.y; acc0[2] += w0 * a0.z; acc0[3] += w0 * a0.w;
            acc0[4] += w0 * a1.x; acc0[5] += w0 * a1.y; acc0[6] += w0 * a1.z; acc0[7] += w0 * a1.w;
            acc1[0] += w1 * a0.x; acc1[1] += w1 * a0.y; acc1[2] += w1 * a0.z; acc1[3] += w1 * a0.w;
            acc1[4] += w1 * a1.x; acc1[5] += w1 * a1.y; acc1[6] += w1 * a1.z; acc1[7] += w1 * a1.w;
        }
        #pragma unroll
        for (int i = 0; i < 8; i++) {
            int c = c0 + i;
            Wd[(size_t)(h * 64 + c) * Dd + R0 + l]      = __float2half(acc0[i]);
            Wd[(size_t)(h * 64 + c) * Dd + R0 + 32 + l] = __float2half(acc1[i]);
        }

        if (R0 == 0 && tid < 64) {
            float bacc = 0.f;
            #pragma unroll 16
            for (int j = 0; j < 64; j++) bacc += bs[h * 64 + j] * At[j][tid];
            bd[h * 64 + tid] = bacc;
        }
    }
}

// ---------------- HMMA tile: 64m x 64n, K=512, 64-k chunks, 3-stage cp.async ----
// Dynamic smem: A 3 planes + B 3 planes of 64x72 halves = 55296 B.
template <int MODE>
__device__ __forceinline__ void mma_tile(const __half* __restrict__ X, int lda,
                                         const __half* __restrict__ BT, int ldb,
                                         const float* __restrict__ bias,
                                         __half* __restrict__ outh,
                                         float* __restrict__ outf,
                                         int m0, int n0, int ldo) {
    extern __shared__ __half mt_smem[];
    const u32 PLANE = 64 * 72 * 2;   // bytes per plane
    u32 abase = (u32)__cvta_generic_to_shared(mt_smem);
    u32 bbase = abase + 3 * PLANE;

    int tid = threadIdx.x, wid = tid >> 5, lane = tid & 31;
    int wm = (wid & 1) * 32, wn = (wid >> 1) * 16;
    int g = lane >> 2, qd = (lane & 3) * 2;
    int sr = tid >> 2, sk = (tid & 3) << 4;        // 64 rows x 64 k-halves
    int lrow = lane & 15, lcol = (lane >> 4) << 3;

    float acc[2][2][4] = {};

    const __half* xg = X + (size_t)(m0 + sr) * lda + sk;
    const __half* bg = BT + (size_t)(n0 + sr) * ldb + sk;
    u32 adst = abase + (sr * 72 + sk) * 2;
    u32 bdst = bbase + (sr * 72 + sk) * 2;

#define STAGE_MT(p, k0) do { \
        cp16(adst + (u32)(p) * PLANE,      xg + (k0)); \
        cp16(adst + (u32)(p) * PLANE + 16, xg + (k0) + 8); \
        cp16(bdst + (u32)(p) * PLANE,      bg + (k0)); \
        cp16(bdst + (u32)(p) * PLANE + 16, bg + (k0) + 8); \
        asm volatile("cp.async.commit_group;"); } while (0)

    STAGE_MT(0, 0);
    STAGE_MT(1, 64);

    int buf = 0;
    for (int ch = 0; ch < 8; ch++) {
        if (ch < 7) asm volatile("cp.async.wait_group 1;");
        else        asm volatile("cp.async.wait_group 0;");
        __syncthreads();
        if (ch + 2 < 8) {
            int nb = buf + 2; if (nb >= 3) nb -= 3;
            STAGE_MT(nb, (ch + 2) * 64);
        }
        u32 abuf = abase + (u32)buf * PLANE;
        u32 bbuf = bbase + (u32)buf * PLANE;
        #pragma unroll
        for (int ks = 0; ks < 64; ks += 16) {
            u32 a[2][4], b[2][2];
            ldsm4(a[0][0], a[0][1], a[0][2], a[0][3],
                  abuf + ((wm + lrow) * 72 + ks + lcol) * 2);
            ldsm4(a[1][0], a[1][1], a[1][2], a[1][3],
                  abuf + ((wm + 16 + lrow) * 72 + ks + lcol) * 2);
            u32 r0, r1, r2, r3;
            ldsm4(r0, r1, r2, r3,
                  bbuf + ((wn + lrow) * 72 + ks + lcol) * 2);
            b[0][0] = r0; b[0][1] = r2; b[1][0] = r1; b[1][1] = r3;
            mma16816(acc[0][0], a[0], b[0]); mma16816(acc[0][1], a[0], b[1]);
            mma16816(acc[1][0], a[1], b[0]); mma16816(acc[1][1], a[1], b[1]);
        }
        if (++buf == 3) buf = 0;
    }
#undef STAGE_MT

    #pragma unroll
    for (int mm = 0; mm < 2; mm++) {
        #pragma unroll
        for (int nn = 0; nn < 2; nn++) {
            int M = m0 + wm + mm * 16;
            int N = n0 + wn + nn * 8 + qd;
            float b0 = bias ? bias[N] : 0.f;
            float b1 = bias ? bias[N + 1] : 0.f;
            float c0 = acc[mm][nn][0] + b0, c1 = acc[mm][nn][1] + b1;
            float c2 = acc[mm][nn][2] + b0, c3 = acc[mm][nn][3] + b1;
            if (MODE == 0) {
                __half2 h01 = __floats2half2_rn(c0, c1);
                __half2 h23 = __floats2half2_rn(c2, c3);
                *(u32*)(outh + (size_t)(M + g) * ldo + N)     = *(u32*)&h01;
                *(u32*)(outh + (size_t)(M + g + 8) * ldo + N) = *(u32*)&h23;
            } else if (MODE == 1) {
                int bb = M >> 9;
                int s = (M & 511) + g;
                int h = N >> 6, dd = N & 63;
                __half* r0 = outh + ((size_t)((bb * Hd + h) * HDd + dd)) * Sd;
                __half* r1 = r0 + Sd;
                r0[s] = __float2half(c0); r1[s] = __float2half(c1);
                r0[s + 8] = __float2half(c2); r1[s + 8] = __float2half(c3);
            } else {
                float2 o0 = { c0, c1 }, o1 = { c2, c3 };
                *(float2*)(outf + (size_t)(M + g) * ldo + N)     = o0;
                *(float2*)(outf + (size_t)(M + g + 8) * ldo + N) = o1;
            }
        }
    }
}

__global__ __launch_bounds__(256) void proj_mma_kernel(const float* __restrict__ bv) {
    int z = blockIdx.z;
    int m0 = blockIdx.y * 64, n0 = blockIdx.x * 64;
    if (z == 0)
        mma_tile<0>(g_xq16, Dd, g_Wqh, Dd, g_bq, g_qth, nullptr, m0, n0, Dd);
    else if (z == 1)
        mma_tile<0>(g_xk16, Dd, g_Wkh, Dd, g_bk, g_kth, nullptr, m0, n0, Dd);
    else
        mma_tile<1>(g_xv16, Dd, g_Wvh, Dd, bv, g_v16T, nullptr, m0, n0, 0);
}

__global__ __launch_bounds__(256) void out_mma_kernel(const float* __restrict__ bo,
                                                      float* __restrict__ out) {
    mma_tile<2>(g_ctx16, Dd, g_Woh, Dd, bo, nullptr, out,
                blockIdx.y * 64, blockIdx.x * 64, Dd);
}

// ---------------- scores + softmax + fused ctx (dynamic smem, 86400 B) ----------
// Layout: ks0 @0 (16384), ks1 @16384, qs @32768 (2048), avh @34816 (128),
//         att @34944 (16640), vbuf[2] @51584 (2 x 17408). No aliasing.
#define SC_QS   32768
#define SC_AVH  34816
#define SC_ATT  34944
#define SC_VB   51584
#define SC_VBS  17408
#define SC_SMEM 86400

__global__ __launch_bounds__(512, 2) void scores_kernel(const float* __restrict__ av,
                                                        float* __restrict__ attn_out) {
    extern __shared__ char smpool[];
    uint4 (*qs4)[8] = (uint4(*)[8])(smpool + SC_QS);
    uint4 *avh4     = (uint4*)(smpool + SC_AVH);
    __half (*att)[520] = (__half(*)[520])(smpool + SC_ATT);

    int b = blockIdx.z, h = blockIdx.y;
    int q0 = blockIdx.x * 16;
    int tid = threadIdx.x;
    int w = tid >> 5, ln = tid & 31;
    int swl = ln & 7;
    int g = ln >> 2, qd = (ln & 3) * 2;

    u32 ksbase = (u32)__cvta_generic_to_shared(smpool);
    u32 vbase  = ksbase + SC_VB;
    const __half* ksrc = g_kth + ((size_t)(b * Sd)) * Dd + h * HDd;
    const __half* vsrc = g_v16T + ((size_t)((b * Hd + h) * HDd)) * Sd;

    // stage k chunk 0 (async, swizzled)
    {
        #pragma unroll
        for (int i = 0; i < 2; i++) {
            int t = tid + i * 512;
            int row = t >> 3, c4 = t & 7;
            cp16(ksbase + (((row << 3) + (c4 ^ (row & 7))) << 4),
                 ksrc + (size_t)row * Dd + c4 * 8);
        }
        asm volatile("cp.async.commit_group;");
    }
    if (tid < 128) {
        int row = tid >> 3, c4 = tid & 7;
        qs4[row][c4] =
            *(const uint4*)(g_qth + ((size_t)(b * Sd + q0 + row)) * Dd + h * HDd + c4 * 8);
    } else if (tid < 160) {
        int i = tid - 128;
        __half2 hh = __floats2half2_rn(av[2 * i], av[2 * i + 1]);
        ((u32*)avh4)[i] = *(u32*)&hh;
    }

    float s[4][4];

    for (int ch = 0; ch < 4; ch++) {
        asm volatile("cp.async.wait_group 0;");
        __syncthreads();
        if (ch < 3) {   // stage k chunk ch+1; at ch==2 also prefetch v tile kc=0
            u32 kb = ksbase + (u32)((ch + 1) & 1) * 16384;
            const __half* src = ksrc + (size_t)(ch + 1) * 128 * Dd;
            #pragma unroll
            for (int i = 0; i < 2; i++) {
                int t = tid + i * 512;
                int row = t >> 3, c4 = t & 7;
                cp16(kb + (((row << 3) + (c4 ^ (row & 7))) << 4),
                     src + (size_t)row * Dd + c4 * 8);
            }
            if (ch == 2) {
                #pragma unroll
                for (int i = 0; i < 2; i++) {
                    int t = tid + i * 512;
                    int dRow = t >> 4, cs = (t & 15) * 8;
                    cp16(vbase + (dRow * 136 + cs) * 2,
                         vsrc + (size_t)dRow * Sd + cs);
                }
            }
            asm volatile("cp.async.commit_group;");
        }

        uint4 (*ks4)[8] = (uint4(*)[8])(smpool + (u32)(ch & 1) * 16384);
        float sa0 = 0.f, sa1 = 0.f, sa2 = 0.f, sa3 = 0.f;
        #pragma unroll
        for (int j = 0; j < 8; j++) {
            uint4 qq = qs4[w][j];
            uint4 aa = avh4[j];
            int sc = j ^ swl;
            uint4 k0 = ks4[ln][sc];
            uint4 k1 = ks4[32 + ln][sc];
            uint4 k2 = ks4[64 + ln][sc];
            uint4 k3 = ks4[96 + ln][sc];
            u32 a0 = 0, a1 = 0, a2 = 0, a3 = 0;
            tchain(qq.x, k0.x, aa.x, a0); tchain(qq.y, k0.y, aa.y, a0);
            tchain(qq.z, k0.z, aa.z, a0); tchain(qq.w, k0.w, aa.w, a0);
            tchain(qq.x, k1.x, aa.x, a1); tchain(qq.y, k1.y, aa.y, a1);
            tchain(qq.z, k1.z, aa.z, a1); tchain(qq.w, k1.w, aa.w, a1);
            tchain(qq.x, k2.x, aa.x, a2); tchain(qq.y, k2.y, aa.y, a2);
            tchain(qq.z, k2.z, aa.z, a2); tchain(qq.w, k2.w, aa.w, a2);
            tchain(qq.x, k3.x, aa.x, a3); tchain(qq.y, k3.y, aa.y, a3);
            tchain(qq.z, k3.z, aa.z, a3); tchain(qq.w, k3.w, aa.w, a3);
            float lo, hi;
            h2f2(a0, lo, hi); sa0 += lo + hi;
            h2f2(a1, lo, hi); sa1 += lo + hi;
            h2f2(a2, lo, hi); sa2 += lo + hi;
            h2f2(a3, lo, hi); sa3 += lo + hi;
        }
        s[ch][0] = sa0; s[ch][1] = sa1; s[ch][2] = sa2; s[ch][3] = sa3;
    }

    // softmax (registers + shuffles only)
    float mx = -1e30f;
    #pragma unroll
    for (int ch = 0; ch < 4; ch++)
        #pragma unroll
        for (int m = 0; m < 4; m++) mx = fmaxf(mx, s[ch][m]);
    #pragma unroll
    for (int o = 16; o > 0; o >>= 1) mx = fmaxf(mx, __shfl_xor_sync(0xffffffffu, mx, o));
    float sum = 0.f;
    #pragma unroll
    for (int ch = 0; ch < 4; ch++)
        #pragma unroll
        for (int m = 0; m < 4; m++) { s[ch][m] = __expf(s[ch][m] - mx); sum += s[ch][m]; }
    #pragma unroll
    for (int o = 16; o > 0; o >>= 1) sum += __shfl_xor_sync(0xffffffffu, sum, o);
    float inv = 1.f / sum;

    // write attn: fp32 -> gmem (required output), f16 -> smem tile (own row, no race)
    size_t rowoff = (((size_t)(b * Hd + h) * Sd) + q0 + w) * Sd;
    float* arow = attn_out + rowoff;
    #pragma unroll
    for (int ch = 0; ch < 4; ch++)
        #pragma unroll
        for (int m = 0; m < 4; m++) {
            float a = s[ch][m] * inv;
            int kk = ch * 128 + m * 32 + ln;
            arow[kk] = a;
            att[w][kk] = __float2half(a);
        }

    // -------- fused ctx: ctx[16 q][64 d] = att[16][512] @ v[512][64] --------
    // vbuf double-buffered; kc=0 tile prefetched during score phase.
    int wn = (w & 7) * 8;
    float cacc[4] = {0.f, 0.f, 0.f, 0.f};

    for (int kc = 0; kc < 4; kc++) {
        asm volatile("cp.async.wait_group 0;");
        __syncthreads();   // att visible (kc==0); vbuf reuse safety (kc>=2)
        if (kc < 3) {
            u32 vb = vbase + (u32)((kc + 1) & 1) * SC_VBS;
            const __half* src = vsrc + (size_t)(kc + 1) * 128;
            #pragma unroll
            for (int i = 0; i < 2; i++) {
                int t = tid + i * 512;
                int dRow = t >> 4, cs = (t & 15) * 8;
                cp16(vb + (dRow * 136 + cs) * 2, src + (size_t)dRow * Sd + cs);
            }
            asm volatile("cp.async.commit_group;");
        }
        if (w < 8) {
            __half (*vbuf)[136] = (__half(*)[136])(smpool + SC_VB + (u32)(kc & 1) * SC_VBS);
            #pragma unroll
            for (int ks = 0; ks < 8; ks++) {
                int kcol = kc * 128 + ks * 16;
                u32 a[4], bf[2];
                a[0] = *(const u32*)&att[g][kcol + qd];
                a[1] = *(const u32*)&att[g + 8][kcol + qd];
                a[2] = *(const u32*)&att[g][kcol + qd + 8];
                a[3] = *(const u32*)&att[g + 8][kcol + qd + 8];
                bf[0] = *(const u32*)&vbuf[wn + g][ks * 16 + qd];
                bf[1] = *(const u32*)&vbuf[wn + g][ks * 16 + qd + 8];
                mma16816(cacc, a, bf);
            }
        }
    }

    if (w < 8) {
        int dcol = h * 64 + wn + qd;
        __half2 h01 = __floats2half2_rn(cacc[0], cacc[1]);
        __half2 h23 = __floats2half2_rn(cacc[2], cacc[3]);
        *(u32*)(g_ctx16 + (size_t)(b * Sd + q0 + g) * Dd + dcol)     = *(u32*)&h01;
        *(u32*)(g_ctx16 + (size_t)(b * Sd + q0 + g + 8) * Dd + dcol) = *(u32*)&h23;
    }
}

// ---------------- launch ----------------
#define MT_SMEM 55296

extern "C" void kernel_launch(void* const* d_in, const int* in_sizes, int n_in,
                              void* d_out, int out_size) {
    const float* query = (const float*)d_in[0];
    const float* key_  = (const float*)d_in[1];
    const float* value = (const float*)d_in[2];
    const float* Wq    = (const float*)d_in[3];
    const float* bq    = (const float*)d_in[4];
    const float* Wk    = (const float*)d_in[5];
    const float* bk    = (const float*)d_in[6];
    const float* Wv    = (const float*)d_in[7];
    const float* bv    = (const float*)d_in[8];
    const float* Wo    = (const float*)d_in[9];
    const float* bo    = (const float*)d_in[10];
    const float* Aq    = (const float*)d_in[11];
    const float* Ak    = (const float*)d_in[12];
    const float* av    = (const float*)d_in[13];

    float* out      = (float*)d_out;                  // [B,S,D]
    float* attn_out = out + (size_t)Bd * Sd * Dd;     // [B,H,S,S]

    cudaFuncSetAttribute(proj_mma_kernel, cudaFuncAttributeMaxDynamicSharedMemorySize, MT_SMEM);
    cudaFuncSetAttribute(out_mma_kernel,  cudaFuncAttributeMaxDynamicSharedMemorySize, MT_SMEM);
    cudaFuncSetAttribute(scores_kernel,   cudaFuncAttributeMaxDynamicSharedMemorySize, SC_SMEM);

    prep_fold_kernel<<<1408, 256>>>(query, key_, value, Wv, Wo,
                                    Wq, Aq, bq, Wk, Ak, bk);
    proj_mma_kernel<<<dim3(8, 16, 3), 256, MT_SMEM>>>(bv);
    scores_kernel<<<dim3(32, Hd, Bd), 512, SC_SMEM>>>(av, attn_out);
    out_mma_kernel<<<dim3(8, 16), 256, MT_SMEM>>>(bo, out);
}